// round 2
// baseline (speedup 1.0000x reference)
#include <cuda_runtime.h>
#include <cstdint>

#define OBS 128
#define H   64
#define AD  8
#define TRIL 36
#define FH  32
#define NL  4
#define ROWS 128
#define THREADS 128
#define XPAD 132

// smem layout (floats)
#define XS_F   (ROWS * XPAD)          // 16896
#define WS_F   (OBS * H)              // 8192 (max weight phase)
#define SFW2_F (NL * FH * AD)         // 1024
#define SCOND_F (NL * 4 * FH)         // 512
#define SFB1_F (NL * FH)              // 128
#define SFB2_F (NL * AD)              // 32
#define SMW_F  (H * AD)               // 512
#define SCW3_F (H)                    // 64
#define SMEM_FLOATS (XS_F + WS_F + SFW2_F + SCOND_F + SFB1_F + SFB2_F + SMW_F + SCW3_F)
#define SMEM_BYTES (SMEM_FLOATS * 4)

struct Params {
    const float *x, *action, *z_rpo;
    const float *cW1, *cb1, *c_rms, *cW2, *cb2, *cW3, *cb3;
    const float *aW1, *ab1, *aW2, *ab2, *mW, *mb;
    const float *tW1, *tb1, *t_rms1, *tW2, *tb2, *t_rms2, *hW, *hb;
    const float *fW1, *fb1, *fW2, *fb2;
    float *out;
    int B;
};

__device__ __forceinline__ float siluf(float v) {
    return v / (1.f + __expf(-v));
}

__device__ __forceinline__ void load_ws4(float* dst, const float* src, int nfloats) {
    const float4* s4 = reinterpret_cast<const float4*>(src);
    float4* d4 = reinterpret_cast<float4*>(dst);
    int n4 = nfloats >> 2;
    for (int i = threadIdx.x; i < n4; i += THREADS) d4[i] = s4[i];
}

// acc[N] += x(smem row, K=4*K4) @ W(smem, KxN row-major)
template<int K4, int N>
__device__ __forceinline__ void gemm_x(const float* __restrict__ xrow,
                                       const float* __restrict__ w,
                                       float* __restrict__ acc) {
#pragma unroll 2
    for (int k4 = 0; k4 < K4; ++k4) {
        float4 xv = *reinterpret_cast<const float4*>(xrow + 4 * k4);
        float xk[4] = {xv.x, xv.y, xv.z, xv.w};
#pragma unroll
        for (int kk = 0; kk < 4; ++kk) {
            const float4* w4 = reinterpret_cast<const float4*>(w + (4 * k4 + kk) * N);
            float xc = xk[kk];
#pragma unroll
            for (int j = 0; j < N / 4; ++j) {
                float4 wv = w4[j];
                acc[4*j+0] = fmaf(xc, wv.x, acc[4*j+0]);
                acc[4*j+1] = fmaf(xc, wv.y, acc[4*j+1]);
                acc[4*j+2] = fmaf(xc, wv.z, acc[4*j+2]);
                acc[4*j+3] = fmaf(xc, wv.w, acc[4*j+3]);
            }
        }
    }
}

// acc[N] += xin(regs, K) @ W(smem, KxN row-major) -- K fully unrolled
template<int K, int N>
__device__ __forceinline__ void gemm_r(const float* __restrict__ xin,
                                       const float* __restrict__ w,
                                       float* __restrict__ acc) {
#pragma unroll
    for (int k = 0; k < K; ++k) {
        float xk = xin[k];
        const float4* w4 = reinterpret_cast<const float4*>(w + k * N);
#pragma unroll
        for (int j = 0; j < N / 4; ++j) {
            float4 wv = w4[j];
            acc[4*j+0] = fmaf(xk, wv.x, acc[4*j+0]);
            acc[4*j+1] = fmaf(xk, wv.y, acc[4*j+1]);
            acc[4*j+2] = fmaf(xk, wv.z, acc[4*j+2]);
            acc[4*j+3] = fmaf(xk, wv.w, acc[4*j+3]);
        }
    }
}

__global__ void __launch_bounds__(THREADS, 2) fused_agent_kernel(Params P) {
    extern __shared__ float sm[];
    float* xs    = sm;
    float* ws    = xs + XS_F;
    float* sfW2  = ws + WS_F;
    float* scond = sfW2 + SFW2_F;
    float* sfb1  = scond + SCOND_F;
    float* sfb2  = sfb1 + SFB1_F;
    float* smW   = sfb2 + SFB2_F;
    float* scW3  = smW + SMW_F;

    const int tid = threadIdx.x;
    const size_t row = (size_t)blockIdx.x * ROWS + tid;
    const size_t Bq = (size_t)P.B;

    // ---- stage x tile (coalesced, pad-132 rows) ----
    {
        const float4* gx = reinterpret_cast<const float4*>(P.x + (size_t)blockIdx.x * ROWS * OBS);
        for (int i = tid; i < ROWS * OBS / 4; i += THREADS) {
            float4 v = gx[i];
            int e = i * 4;
            int r = e >> 7;      // /OBS
            int c = e & 127;     // %OBS
            float* dst = xs + r * XPAD + c;
            dst[0] = v.x; dst[1] = v.y; dst[2] = v.z; dst[3] = v.w;
        }
    }
    // ---- static small weights ----
    for (int i = tid; i < SFW2_F; i += THREADS) sfW2[i] = P.fW2[i];
    for (int i = tid; i < SCOND_F; i += THREADS) {
        int l = i >> 7, r = (i >> 5) & 3, j = i & 31;
        scond[i] = P.fW1[(l * 132 + r) * 32 + j];
    }
    for (int i = tid; i < SFB1_F; i += THREADS) sfb1[i] = P.fb1[i];
    if (tid < SFB2_F) sfb2[tid] = P.fb2[tid];
    for (int i = tid; i < SMW_F; i += THREADS) smW[i] = P.mW[i];
    if (tid < SCW3_F) scW3[tid] = P.cW3[tid];
    load_ws4(ws, P.aW1, OBS * H);
    __syncthreads();

    const float* xrow = xs + tid * XPAD;

    // ---------- actor trunk ----------
    float h1[H], h2[H];
#pragma unroll
    for (int j = 0; j < H; ++j) h1[j] = __ldg(P.ab1 + j);
    gemm_x<OBS/4, H>(xrow, ws, h1);
#pragma unroll
    for (int j = 0; j < H; ++j) h1[j] = siluf(h1[j]);

    __syncthreads();
    load_ws4(ws, P.aW2, H * H);
    __syncthreads();
#pragma unroll
    for (int j = 0; j < H; ++j) h2[j] = __ldg(P.ab2 + j);
    gemm_r<H, H>(h1, ws, h2);
#pragma unroll
    for (int j = 0; j < H; ++j) h2[j] = siluf(h2[j]);

    // action_mean + noise
    float am[AD];
#pragma unroll
    for (int m = 0; m < AD; ++m) am[m] = __ldg(P.mb + m);
    gemm_r<H, AD>(h2, smW, am);

    float4 a0 = *reinterpret_cast<const float4*>(P.action + row * AD);
    float4 a1 = *reinterpret_cast<const float4*>(P.action + row * AD + 4);
    float4 z0 = *reinterpret_cast<const float4*>(P.z_rpo + row * AD);
    float4 z1 = *reinterpret_cast<const float4*>(P.z_rpo + row * AD + 4);
    // output: action copy now
    *reinterpret_cast<float4*>(P.out + row * AD) = a0;
    *reinterpret_cast<float4*>(P.out + row * AD + 4) = a1;

    float x1v[4], x2v[4];
    x1v[0] = a0.x - am[0] - z0.x;
    x1v[1] = a0.y - am[1] - z0.y;
    x1v[2] = a0.z - am[2] - z0.z;
    x1v[3] = a0.w - am[3] - z0.w;
    x2v[0] = a1.x - am[4] - z1.x;
    x2v[1] = a1.y - am[5] - z1.y;
    x2v[2] = a1.z - am[6] - z1.z;
    x2v[3] = a1.w - am[7] - z1.w;

    const float EPSF = 1.1920928955078125e-07f;

    // ---------- t-net ----------
    __syncthreads();
    load_ws4(ws, P.tW1, OBS * H);
    __syncthreads();
#pragma unroll
    for (int j = 0; j < H; ++j) h1[j] = __ldg(P.tb1 + j);
    gemm_x<OBS/4, H>(xrow, ws, h1);
    {
        float ss = 0.f;
#pragma unroll
        for (int j = 0; j < H; ++j) { h1[j] = siluf(h1[j]); ss += h1[j] * h1[j]; }
        float sc = rsqrtf(ss * (1.f / H) + EPSF);
#pragma unroll
        for (int j = 0; j < H; ++j) h1[j] = h1[j] * sc * __ldg(P.t_rms1 + j);
    }
    __syncthreads();
    load_ws4(ws, P.tW2, H * H);
    __syncthreads();
#pragma unroll
    for (int j = 0; j < H; ++j) h2[j] = __ldg(P.tb2 + j);
    gemm_r<H, H>(h1, ws, h2);
    {
        float ss = 0.f;
#pragma unroll
        for (int j = 0; j < H; ++j) { h2[j] = siluf(h2[j]); ss += h2[j] * h2[j]; }
        float sc = rsqrtf(ss * (1.f / H) + EPSF);
#pragma unroll
        for (int j = 0; j < H; ++j) h2[j] = h2[j] * sc * __ldg(P.t_rms2 + j);
    }
    __syncthreads();
    load_ws4(ws, P.hW, H * TRIL);
    __syncthreads();
    float Lm[TRIL];
#pragma unroll
    for (int t = 0; t < TRIL; ++t) Lm[t] = __ldg(P.hb + t);
    gemm_r<H, TRIL>(h2, ws, Lm);
    float log_det = 0.f;
#pragma unroll
    for (int i = 0; i < AD; ++i) {
        int d = i * (i + 3) / 2;                       // diag index in tril order
        float r = Lm[d];
        float sp = fmaxf(r, 0.f) + log1pf(__expf(-fabsf(r)));  // softplus (logaddexp(x,0))
        Lm[d] = sp;
        log_det += __logf(sp);
    }

    // ---------- flow (reversed i = 3..0, fully unrolled) ----------
    float fld = 0.f;
#pragma unroll
    for (int it = 0; it < NL; ++it) {
        const int i = NL - 1 - it;
        __syncthreads();
        load_ws4(ws, P.fW1 + ((size_t)i * 132 + 4) * 32, OBS * FH);
        __syncthreads();
        float u[FH];
#pragma unroll
        for (int j = 0; j < FH; ++j) u[j] = sfb1[i * FH + j];
        gemm_x<OBS/4, FH>(xrow, ws, u);
        float* condp = (i % 2 == 0) ? x1v : x2v;
        float* yp    = (i % 2 == 0) ? x2v : x1v;
#pragma unroll
        for (int c = 0; c < 4; ++c) {
            float cv = condp[c];
#pragma unroll
            for (int j = 0; j < FH; ++j)
                u[j] = fmaf(cv, scond[i * 128 + c * 32 + j], u[j]);
        }
#pragma unroll
        for (int j = 0; j < FH; ++j) u[j] = siluf(u[j]);
        float st[8];
#pragma unroll
        for (int m = 0; m < 8; ++m) st[m] = sfb2[i * 8 + m];
        gemm_r<FH, 8>(u, sfW2 + i * FH * 8, st);
#pragma unroll
        for (int m = 0; m < 4; ++m) {
            float s = 2.f * tanhf(st[m]);
            fld += s;
            yp[m] = (yp[m] - st[4 + m]) * __expf(-s);
        }
    }

    // ---------- triangular solve + log_prob/entropy ----------
    float corr[8] = {x1v[0], x1v[1], x1v[2], x1v[3], x2v[0], x2v[1], x2v[2], x2v[3]};
    float zv[8];
#pragma unroll
    for (int i = 0; i < 8; ++i) {
        float acc = corr[i];
#pragma unroll
        for (int j = 0; j < 8; ++j)
            if (j < i) acc -= Lm[i * (i + 1) / 2 + j] * zv[j];
        zv[i] = acc / Lm[i * (i + 1) / 2 + i];
    }
    float mahal = 0.f;
#pragma unroll
    for (int i = 0; i < 8; ++i) mahal += zv[i] * zv[i];
    const float LOG2PIf = 1.8378770664093453f;
    float lp  = -0.5f * (8.f * LOG2PIf + mahal) - log_det - fld;
    float ent = 0.5f * (8.f * (1.f + LOG2PIf)) + log_det + fld;

    // ---------- critic ----------
    __syncthreads();
    load_ws4(ws, P.cW1, OBS * H);
    __syncthreads();
#pragma unroll
    for (int j = 0; j < H; ++j) h1[j] = __ldg(P.cb1 + j);
    gemm_x<OBS/4, H>(xrow, ws, h1);
    {
        float ss = 0.f;
#pragma unroll
        for (int j = 0; j < H; ++j) { h1[j] = siluf(h1[j]); ss += h1[j] * h1[j]; }
        float sc = rsqrtf(ss * (1.f / H) + EPSF);
#pragma unroll
        for (int j = 0; j < H; ++j) h1[j] = h1[j] * sc * __ldg(P.c_rms + j);
    }
    __syncthreads();
    load_ws4(ws, P.cW2, H * H);
    __syncthreads();
#pragma unroll
    for (int j = 0; j < H; ++j) h2[j] = __ldg(P.cb2 + j);
    gemm_r<H, H>(h1, ws, h2);
    float v = __ldg(P.cb3);
#pragma unroll
    for (int k = 0; k < H; ++k) v = fmaf(siluf(h2[k]), scW3[k], v);

    // ---------- scalar outputs ----------
    P.out[Bq * 8 + row]  = lp;
    P.out[Bq * 9 + row]  = ent;
    P.out[Bq * 10 + row] = v;
}

extern "C" void kernel_launch(void* const* d_in, const int* in_sizes, int n_in,
                              void* d_out, int out_size) {
    (void)n_in; (void)out_size;
    Params P;
    P.x      = (const float*)d_in[0];
    P.action = (const float*)d_in[1];
    P.z_rpo  = (const float*)d_in[2];
    P.cW1    = (const float*)d_in[3];
    P.cb1    = (const float*)d_in[4];
    P.c_rms  = (const float*)d_in[5];
    P.cW2    = (const float*)d_in[6];
    P.cb2    = (const float*)d_in[7];
    P.cW3    = (const float*)d_in[8];
    P.cb3    = (const float*)d_in[9];
    P.aW1    = (const float*)d_in[10];
    P.ab1    = (const float*)d_in[11];
    P.aW2    = (const float*)d_in[12];
    P.ab2    = (const float*)d_in[13];
    P.mW     = (const float*)d_in[14];
    P.mb     = (const float*)d_in[15];
    P.tW1    = (const float*)d_in[16];
    P.tb1    = (const float*)d_in[17];
    P.t_rms1 = (const float*)d_in[18];
    P.tW2    = (const float*)d_in[19];
    P.tb2    = (const float*)d_in[20];
    P.t_rms2 = (const float*)d_in[21];
    P.hW     = (const float*)d_in[22];
    P.hb     = (const float*)d_in[23];
    P.fW1    = (const float*)d_in[24];
    P.fb1    = (const float*)d_in[25];
    P.fW2    = (const float*)d_in[26];
    P.fb2    = (const float*)d_in[27];
    P.out    = (float*)d_out;
    P.B      = in_sizes[0] / OBS;

    cudaFuncSetAttribute(fused_agent_kernel,
                         cudaFuncAttributeMaxDynamicSharedMemorySize, SMEM_BYTES);
    fused_agent_kernel<<<P.B / ROWS, THREADS, SMEM_BYTES>>>(P);
}

// round 5
// speedup vs baseline: 2.0173x; 2.0173x over previous
#include <cuda_runtime.h>
#include <cstdint>

#define THREADS 256
#define ROWS 128
#define OBS 128
#define H 64
#define AD 8
#define FH 32
#define NL 4

// ---------------- smem layout (floats) ----------------
#define XS_OFF    0                 // X A-frags: 8 mtiles * 16 kt * 128 = 16384
#define XS_F      16384
#define WBA_OFF   (XS_OFF + XS_F)   // weight buf A: 8192
#define WBA_F     8192
#define WBB_OFF   (WBA_OFF + WBA_F) // weight buf B: 6656
#define WBB_F     6656
#define ACTA_OFF  (WBB_OFF + WBB_F) // act A-frags: 8192
#define ACTA_F    8192
#define ACTB_OFF  (ACTA_OFF + ACTA_F)
#define ACTB_F    8192
#define AMV_OFF   (ACTB_OFF + ACTB_F) // [128][12]: mean 0..7, v at 8
#define AMV_F     (128*12)
#define LR_OFF    (AMV_OFF + AMV_F)   // [128][40]
#define LR_F      (128*40)
#define CST_OFF   (LR_OFF + LR_F)
// consts sublayout (relative to CST_OFF)
#define C_FCOND 0      // 4*4*32 = 512
#define C_FW2   512    // 4*32*8 = 2048
#define C_FB1   2560   // 128
#define C_FB2   2688   // 32
#define C_AB1   2720
#define C_AB2   2784
#define C_MB    2848   // 8
#define C_TB1   2856
#define C_TB2   2920
#define C_TR1   2984
#define C_TR2   3048
#define C_HBP   3112   // 40
#define C_CB1   3152
#define C_CB2   3216
#define C_CRMS  3280
#define C_VB    3344   // 8
#define CST_F   3352
#define SMEM_F  (CST_OFF + CST_F)
#define SMEM_BYTES (SMEM_F * 4)

struct Params {
    const float *x, *action, *z_rpo;
    const float *cW1, *cb1, *c_rms, *cW2, *cb2, *cW3, *cb3;
    const float *aW1, *ab1, *aW2, *ab2, *mW, *mb;
    const float *tW1, *tb1, *t_rms1, *tW2, *tb2, *t_rms2, *hW, *hb;
    const float *fW1, *fb1, *fW2, *fb2;
    float *out;
    int B;
};

__device__ __forceinline__ float siluf(float v) { return v / (1.f + __expf(-v)); }

__device__ __forceinline__ float to_tf32(float f) {
    uint32_t o;
    asm("cvt.rna.tf32.f32 %0, %1;" : "=r"(o) : "f"(f));
    return __uint_as_float(o);
}

__device__ __forceinline__ void cpa4(float* smem_dst, const float* gsrc) {
    uint32_t s = (uint32_t)__cvta_generic_to_shared(smem_dst);
    asm volatile("cp.async.ca.shared.global [%0], [%1], 4;" :: "r"(s), "l"(gsrc));
}
__device__ __forceinline__ void cp_commit() { asm volatile("cp.async.commit_group;"); }
template<int N> __device__ __forceinline__ void cp_wait() {
    asm volatile("cp.async.wait_group %0;" :: "n"(N));
}

// ---- stage weight [K][NR] (row-major) into B-fragment layout, pad cols to NP ----
template<int K, int NP, int NR, int NT>
__device__ __forceinline__ void stage_B(float* dst, const float* g, int tid) {
    constexpr int TOT = K * NP;
    for (int i = tid; i < TOT; i += THREADS) {
        int k = i / NP, n = i % NP;
        int pos = (((k >> 3) * NT + (n >> 3)) * 32 + (n & 7) * 4 + (k & 3)) * 2 + ((k >> 2) & 1);
        if (NP == NR || n < NR) cpa4(dst + pos, g + k * NR + n);
        else dst[pos] = 0.f;
    }
}

__device__ __forceinline__ void cvtpass(float* w, int n, int tid) {
    for (int i = tid; i < n; i += THREADS) w[i] = to_tf32(w[i]);
}

// ---- tf32 mma m16n8k8 ----
__device__ __forceinline__ void mma8(float* c, uint32_t a0, uint32_t a1, uint32_t a2, uint32_t a3,
                                     uint32_t b0, uint32_t b1) {
    asm volatile("mma.sync.aligned.m16n8k8.row.col.f32.tf32.tf32.f32 "
                 "{%0,%1,%2,%3}, {%4,%5,%6,%7}, {%8,%9}, {%0,%1,%2,%3};"
                 : "+f"(c[0]), "+f"(c[1]), "+f"(c[2]), "+f"(c[3])
                 : "r"(a0), "r"(a1), "r"(a2), "r"(a3), "r"(b0), "r"(b1));
}

template<int KT, int NT>
__device__ __forceinline__ void gemm_frag(const float* __restrict__ A, const float* __restrict__ B,
                                          const float* __restrict__ bias,
                                          float (&acc)[NT][4], int lane, int t) {
#pragma unroll
    for (int nt = 0; nt < NT; ++nt) {
        float b0 = bias[nt * 8 + 2 * t], b1 = bias[nt * 8 + 2 * t + 1];
        acc[nt][0] = b0; acc[nt][1] = b1; acc[nt][2] = b0; acc[nt][3] = b1;
    }
#pragma unroll 4
    for (int kt = 0; kt < KT; ++kt) {
        float4 av = *reinterpret_cast<const float4*>(A + (kt * 32 + lane) * 4);
        uint32_t a0 = __float_as_uint(av.x), a1 = __float_as_uint(av.y);
        uint32_t a2 = __float_as_uint(av.z), a3 = __float_as_uint(av.w);
#pragma unroll
        for (int nt = 0; nt < NT; ++nt) {
            float2 bv = *reinterpret_cast<const float2*>(B + ((kt * NT + nt) * 32 + lane) * 2);
            mma8(acc[nt], a0, a1, a2, a3, __float_as_uint(bv.x), __float_as_uint(bv.y));
        }
    }
}

// store one value into A-fragment layout (KT=8 buffers)
__device__ __forceinline__ void store_act(float* buf, int warp, int rl, int col, float v) {
    int kt = col >> 3, kin = col & 7;
    buf[(((warp << 3) + kt) * 32 + ((rl & 7) << 2) + (kin & 3)) * 4 +
        ((rl >> 3) & 1) + (((kin >> 2) & 1) << 1)] = v;
}

// epilogue: silu -> tf32 -> act frags (NT=8)
__device__ __forceinline__ void epi_silu(float (&acc)[8][4], float* dst, int warp, int g, int t) {
#pragma unroll
    for (int nt = 0; nt < 8; ++nt) {
        int c0 = nt * 8 + 2 * t;
        store_act(dst, warp, g,     c0,     to_tf32(siluf(acc[nt][0])));
        store_act(dst, warp, g,     c0 + 1, to_tf32(siluf(acc[nt][1])));
        store_act(dst, warp, g + 8, c0,     to_tf32(siluf(acc[nt][2])));
        store_act(dst, warp, g + 8, c0 + 1, to_tf32(siluf(acc[nt][3])));
    }
}

// epilogue: silu + rms(w) -> tf32 -> act frags
__device__ __forceinline__ void epi_silu_rms(float (&acc)[8][4], float* dst, const float* w,
                                             int warp, int g, int t) {
    float s_lo = 0.f, s_hi = 0.f;
#pragma unroll
    for (int nt = 0; nt < 8; ++nt) {
        acc[nt][0] = siluf(acc[nt][0]); acc[nt][1] = siluf(acc[nt][1]);
        acc[nt][2] = siluf(acc[nt][2]); acc[nt][3] = siluf(acc[nt][3]);
        s_lo += acc[nt][0] * acc[nt][0] + acc[nt][1] * acc[nt][1];
        s_hi += acc[nt][2] * acc[nt][2] + acc[nt][3] * acc[nt][3];
    }
    s_lo += __shfl_xor_sync(0xffffffffu, s_lo, 1);
    s_lo += __shfl_xor_sync(0xffffffffu, s_lo, 2);
    s_hi += __shfl_xor_sync(0xffffffffu, s_hi, 1);
    s_hi += __shfl_xor_sync(0xffffffffu, s_hi, 2);
    const float EPSF = 1.1920928955078125e-07f;
    float sc_lo = rsqrtf(s_lo * (1.f / 64.f) + EPSF);
    float sc_hi = rsqrtf(s_hi * (1.f / 64.f) + EPSF);
#pragma unroll
    for (int nt = 0; nt < 8; ++nt) {
        int c0 = nt * 8 + 2 * t;
        store_act(dst, warp, g,     c0,     to_tf32(acc[nt][0] * sc_lo * w[c0]));
        store_act(dst, warp, g,     c0 + 1, to_tf32(acc[nt][1] * sc_lo * w[c0 + 1]));
        store_act(dst, warp, g + 8, c0,     to_tf32(acc[nt][2] * sc_hi * w[c0]));
        store_act(dst, warp, g + 8, c0 + 1, to_tf32(acc[nt][3] * sc_hi * w[c0 + 1]));
    }
}

__global__ void __launch_bounds__(THREADS) fused_agent_tc(Params P) {
    extern __shared__ float sm[];
    float* xs   = sm + XS_OFF;
    float* wbA  = sm + WBA_OFF;
    float* wbB  = sm + WBB_OFF;
    float* actA = sm + ACTA_OFF;
    float* actB = sm + ACTB_OFF;
    float* amv  = sm + AMV_OFF;
    float* lr   = sm + LR_OFF;
    float* cst  = sm + CST_OFF;

    const int tid = threadIdx.x;
    const int warp = tid >> 5;
    const int lane = tid & 31;
    const int g = lane >> 2;
    const int t = lane & 3;

    // ---- prefetch first two weight groups (async) ----
    stage_B<128, 64, 64, 8>(wbA, P.aW1, tid); cp_commit();                 // g1
    stage_B<64, 64, 64, 8>(wbB, P.aW2, tid);
    stage_B<64, 8, 8, 1>(wbB + 4096, P.mW, tid); cp_commit();              // g2

    // ---- stage X into A-fragment layout (tf32-rounded) ----
    {
        const float* gx = P.x + (size_t)blockIdx.x * ROWS * OBS;
        for (int i = tid; i < ROWS * OBS; i += THREADS) {
            int row = i >> 7, col = i & 127;
            float v = to_tf32(gx[i]);
            int mt = row >> 4, kt = col >> 3, kin = col & 7;
            xs[((mt * 16 + kt) * 32 + (row & 7) * 4 + (kin & 3)) * 4 +
               ((row >> 3) & 1) + (((kin >> 2) & 1) << 1)] = v;
        }
    }
    // ---- stage consts (plain) ----
    for (int i = tid; i < 512; i += THREADS)
        cst[C_FCOND + i] = P.fW1[((i >> 7) * 132 + ((i >> 5) & 3)) * 32 + (i & 31)];
    for (int i = tid; i < 2048; i += THREADS) cst[C_FW2 + i] = P.fW2[i];
    for (int i = tid; i < 128; i += THREADS) cst[C_FB1 + i] = P.fb1[i];
    if (tid < 32) cst[C_FB2 + tid] = P.fb2[tid];
    if (tid < 64) {
        cst[C_AB1 + tid] = P.ab1[tid]; cst[C_AB2 + tid] = P.ab2[tid];
        cst[C_TB1 + tid] = P.tb1[tid]; cst[C_TB2 + tid] = P.tb2[tid];
        cst[C_TR1 + tid] = P.t_rms1[tid]; cst[C_TR2 + tid] = P.t_rms2[tid];
        cst[C_CB1 + tid] = P.cb1[tid]; cst[C_CB2 + tid] = P.cb2[tid];
        cst[C_CRMS + tid] = P.c_rms[tid];
    }
    if (tid < 8) cst[C_MB + tid] = P.mb[tid];
    if (tid < 40) cst[C_HBP + tid] = (tid < 36) ? P.hb[tid] : 0.f;
    if (tid < 8) cst[C_VB + tid] = (tid == 0) ? P.cb3[0] : 0.f;

    cp_wait<1>(); __syncthreads();
    cvtpass(wbA, 8192, tid); __syncthreads();

    // ===== A1 = silu(X @ aW1 + ab1) =====
    {
        float acc[8][4];
        gemm_frag<16, 8>(xs + warp * 2048, wbA, cst + C_AB1, acc, lane, t);
        epi_silu(acc, actA, warp, g, t);
    }
    __syncthreads();
    stage_B<128, 64, 64, 8>(wbA, P.tW1, tid); cp_commit();                 // g3
    cp_wait<1>(); __syncthreads();
    cvtpass(wbB, 4608, tid); __syncthreads();

    // ===== A2 = silu(A1 @ aW2 + ab2) =====
    {
        float acc[8][4];
        gemm_frag<8, 8>(actA + warp * 1024, wbB, cst + C_AB2, acc, lane, t);
        epi_silu(acc, actB, warp, g, t);
    }
    __syncthreads();
    // ===== AM = A2 @ mW + mb =====
    {
        float acc[1][4];
        gemm_frag<8, 1>(actB + warp * 1024, wbB + 4096, cst + C_MB, acc, lane, t);
        int rlo = warp * 16 + g, rhi = rlo + 8, c0 = 2 * t;
        amv[rlo * 12 + c0] = acc[0][0]; amv[rlo * 12 + c0 + 1] = acc[0][1];
        amv[rhi * 12 + c0] = acc[0][2]; amv[rhi * 12 + c0 + 1] = acc[0][3];
    }
    __syncthreads();
    stage_B<64, 64, 64, 8>(wbB, P.tW2, tid);
    stage_B<64, 40, 36, 5>(wbB + 4096, P.hW, tid); cp_commit();            // g4
    cp_wait<1>(); __syncthreads();
    cvtpass(wbA, 8192, tid); __syncthreads();

    // ===== T1 = rms(silu(X @ tW1 + tb1), t_rms1) =====
    {
        float acc[8][4];
        gemm_frag<16, 8>(xs + warp * 2048, wbA, cst + C_TB1, acc, lane, t);
        epi_silu_rms(acc, actA, cst + C_TR1, warp, g, t);
    }
    __syncthreads();
    stage_B<128, 64, 64, 8>(wbA, P.cW1, tid); cp_commit();                 // g5
    cp_wait<1>(); __syncthreads();
    cvtpass(wbB, 6656, tid); __syncthreads();

    // ===== T2 = rms(silu(T1 @ tW2 + tb2), t_rms2) =====
    {
        float acc[8][4];
        gemm_frag<8, 8>(actA + warp * 1024, wbB, cst + C_TB2, acc, lane, t);
        epi_silu_rms(acc, actB, cst + C_TR2, warp, g, t);
    }
    __syncthreads();
    // ===== Lraw = T2 @ hW + hb (cols padded to 40) =====
    {
        float acc[5][4];
        gemm_frag<8, 5>(actB + warp * 1024, wbB + 4096, cst + C_HBP, acc, lane, t);
        int rlo = warp * 16 + g, rhi = rlo + 8;
#pragma unroll
        for (int nt = 0; nt < 5; ++nt) {
            int c0 = nt * 8 + 2 * t;
            lr[rlo * 40 + c0] = acc[nt][0]; lr[rlo * 40 + c0 + 1] = acc[nt][1];
            lr[rhi * 40 + c0] = acc[nt][2]; lr[rhi * 40 + c0 + 1] = acc[nt][3];
        }
    }
    __syncthreads();
    stage_B<64, 64, 64, 8>(wbB, P.cW2, tid);
    stage_B<64, 8, 1, 1>(wbB + 4096, P.cW3, tid); cp_commit();             // g6
    cp_wait<1>(); __syncthreads();
    cvtpass(wbA, 8192, tid); __syncthreads();

    // ===== C1 = rms(silu(X @ cW1 + cb1), c_rms) =====
    {
        float acc[8][4];
        gemm_frag<16, 8>(xs + warp * 2048, wbA, cst + C_CB1, acc, lane, t);
        epi_silu_rms(acc, actA, cst + C_CRMS, warp, g, t);
    }
    __syncthreads();
    stage_B<128, 32, 32, 4>(wbA,        P.fW1 + (size_t)(3 * 132 + 4) * 32, tid);
    stage_B<128, 32, 32, 4>(wbA + 4096, P.fW1 + (size_t)(2 * 132 + 4) * 32, tid); cp_commit(); // g7
    cp_wait<1>(); __syncthreads();
    cvtpass(wbB, 4608, tid); __syncthreads();

    // ===== C2 = silu(C1 @ cW2 + cb2) =====
    {
        float acc[8][4];
        gemm_frag<8, 8>(actA + warp * 1024, wbB, cst + C_CB2, acc, lane, t);
        epi_silu(acc, actB, warp, g, t);
    }
    __syncthreads();
    // ===== v = C2 @ cW3 + cb3 =====
    {
        float acc[1][4];
        gemm_frag<8, 1>(actB + warp * 1024, wbB + 4096, cst + C_VB, acc, lane, t);
        if (t == 0) {
            int rlo = warp * 16 + g, rhi = rlo + 8;
            amv[rlo * 12 + 8] = acc[0][0];
            amv[rhi * 12 + 8] = acc[0][2];
        }
    }
    __syncthreads();
    stage_B<128, 32, 32, 4>(wbB, P.fW1 + (size_t)(1 * 132 + 4) * 32, tid); cp_commit(); // g8
    cp_wait<1>(); __syncthreads();
    cvtpass(wbA, 8192, tid); __syncthreads();

    // ===== U3, U2 = X @ fW1[l][4:] + fb1[l] (raw, into act region, swizzled) =====
    float* ub = actA;  // 4 layers * 128 rows * 32 cols, swizzled
#pragma unroll
    for (int li = 0; li < 2; ++li) {
        int l = 3 - li;
        float acc[4][4];
        gemm_frag<16, 4>(xs + warp * 2048, wbA + li * 4096, cst + C_FB1 + l * 32, acc, lane, t);
        int rlo = warp * 16 + g, rhi = rlo + 8;
#pragma unroll
        for (int nt = 0; nt < 4; ++nt) {
            int c0 = nt * 8 + 2 * t;
            ub[(l * 128 + rlo) * 32 + ((c0 + rlo) & 31)]     = acc[nt][0];
            ub[(l * 128 + rlo) * 32 + ((c0 + 1 + rlo) & 31)] = acc[nt][1];
            ub[(l * 128 + rhi) * 32 + ((c0 + rhi) & 31)]     = acc[nt][2];
            ub[(l * 128 + rhi) * 32 + ((c0 + 1 + rhi) & 31)] = acc[nt][3];
        }
    }
    __syncthreads();
    stage_B<128, 32, 32, 4>(wbA, P.fW1 + (size_t)(0 * 132 + 4) * 32, tid); cp_commit(); // g9
    cp_wait<1>(); __syncthreads();
    cvtpass(wbB, 4096, tid); __syncthreads();

    // ===== U1 =====
    {
        const int l = 1;
        float acc[4][4];
        gemm_frag<16, 4>(xs + warp * 2048, wbB, cst + C_FB1 + l * 32, acc, lane, t);
        int rlo = warp * 16 + g, rhi = rlo + 8;
#pragma unroll
        for (int nt = 0; nt < 4; ++nt) {
            int c0 = nt * 8 + 2 * t;
            ub[(l * 128 + rlo) * 32 + ((c0 + rlo) & 31)]     = acc[nt][0];
            ub[(l * 128 + rlo) * 32 + ((c0 + 1 + rlo) & 31)] = acc[nt][1];
            ub[(l * 128 + rhi) * 32 + ((c0 + rhi) & 31)]     = acc[nt][2];
            ub[(l * 128 + rhi) * 32 + ((c0 + 1 + rhi) & 31)] = acc[nt][3];
        }
    }
    __syncthreads();
    cp_wait<0>(); __syncthreads();
    cvtpass(wbA, 4096, tid); __syncthreads();
    // ===== U0 =====
    {
        const int l = 0;
        float acc[4][4];
        gemm_frag<16, 4>(xs + warp * 2048, wbA, cst + C_FB1 + l * 32, acc, lane, t);
        int rlo = warp * 16 + g, rhi = rlo + 8;
#pragma unroll
        for (int nt = 0; nt < 4; ++nt) {
            int c0 = nt * 8 + 2 * t;
            ub[(l * 128 + rlo) * 32 + ((c0 + rlo) & 31)]     = acc[nt][0];
            ub[(l * 128 + rlo) * 32 + ((c0 + 1 + rlo) & 31)] = acc[nt][1];
            ub[(l * 128 + rhi) * 32 + ((c0 + rhi) & 31)]     = acc[nt][2];
            ub[(l * 128 + rhi) * 32 + ((c0 + 1 + rhi) & 31)] = acc[nt][3];
        }
    }
    __syncthreads();

    // =================== SIMT tail: 2 threads per row ===================
    const int r = warp * 16 + (lane >> 1);
    const int half = lane & 1;
    const size_t grow = (size_t)blockIdx.x * ROWS + r;
    const size_t Bq = (size_t)P.B;

    float4 a0 = *reinterpret_cast<const float4*>(P.action + grow * 8);
    float4 a1 = *reinterpret_cast<const float4*>(P.action + grow * 8 + 4);
    float4 z0 = *reinterpret_cast<const float4*>(P.z_rpo + grow * 8);
    float4 z1 = *reinterpret_cast<const float4*>(P.z_rpo + grow * 8 + 4);

    float x1v[4], x2v[4];
    x1v[0] = a0.x - amv[r * 12 + 0] - z0.x;
    x1v[1] = a0.y - amv[r * 12 + 1] - z0.y;
    x1v[2] = a0.z - amv[r * 12 + 2] - z0.z;
    x1v[3] = a0.w - amv[r * 12 + 3] - z0.w;
    x2v[0] = a1.x - amv[r * 12 + 4] - z1.x;
    x2v[1] = a1.y - amv[r * 12 + 5] - z1.y;
    x2v[2] = a1.z - amv[r * 12 + 6] - z1.z;
    x2v[3] = a1.w - amv[r * 12 + 7] - z1.w;

    const float* fcond = cst + C_FCOND;
    const float* fW2s  = cst + C_FW2;
    const float* fb2s  = cst + C_FB2;

    float fld = 0.f;
#pragma unroll
    for (int it = 0; it < NL; ++it) {
        const int i = NL - 1 - it;
        float* condp = (i % 2 == 0) ? x1v : x2v;
        float* yp    = (i % 2 == 0) ? x2v : x1v;
        float u[16];
#pragma unroll
        for (int jj = 0; jj < 16; ++jj) {
            int j = half * 16 + jj;
            u[jj] = ub[(i * 128 + r) * 32 + ((j + r) & 31)];
        }
#pragma unroll
        for (int c = 0; c < 4; ++c) {
            float cv = condp[c];
#pragma unroll
            for (int jj = 0; jj < 16; ++jj)
                u[jj] = fmaf(cv, fcond[(i * 4 + c) * 32 + half * 16 + jj], u[jj]);
        }
#pragma unroll
        for (int jj = 0; jj < 16; ++jj) u[jj] = siluf(u[jj]);
        float stp[8];
#pragma unroll
        for (int m = 0; m < 8; ++m) stp[m] = (half == 0) ? fb2s[i * 8 + m] : 0.f;
#pragma unroll
        for (int jj = 0; jj < 16; ++jj) {
            float uv = u[jj];
            const float* wrow = fW2s + (i * 32 + half * 16 + jj) * 8;
#pragma unroll
            for (int m = 0; m < 8; ++m) stp[m] = fmaf(uv, wrow[m], stp[m]);
        }
#pragma unroll
        for (int m = 0; m < 8; ++m) stp[m] += __shfl_xor_sync(0xffffffffu, stp[m], 1);
#pragma unroll
        for (int m = 0; m < 4; ++m) {
            float s = 2.f * tanhf(stp[m]);
            fld += s;
            yp[m] = (yp[m] - stp[4 + m]) * __expf(-s);
        }
    }

    // triangular processing
    float Lm[36];
#pragma unroll
    for (int i = 0; i < 36; ++i) Lm[i] = lr[r * 40 + i];
    float log_det = 0.f;
#pragma unroll
    for (int i = 0; i < 8; ++i) {
        int d = i * (i + 3) / 2;
        float rv = Lm[d];
        float sp = fmaxf(rv, 0.f) + log1pf(__expf(-fabsf(rv)));
        Lm[d] = sp;
        log_det += __logf(sp);
    }
    float corr[8] = {x1v[0], x1v[1], x1v[2], x1v[3], x2v[0], x2v[1], x2v[2], x2v[3]};
    float zv[8];
#pragma unroll
    for (int i = 0; i < 8; ++i) {
        float acc = corr[i];
#pragma unroll
        for (int j = 0; j < 8; ++j)
            if (j < i) acc -= Lm[i * (i + 1) / 2 + j] * zv[j];
        zv[i] = acc / Lm[i * (i + 1) / 2 + i];
    }
    float mahal = 0.f;
#pragma unroll
    for (int i = 0; i < 8; ++i) mahal += zv[i] * zv[i];
    const float LOG2PIf = 1.8378770664093453f;
    float lp  = -0.5f * (8.f * LOG2PIf + mahal) - log_det - fld;
    float ent = 0.5f * (8.f * (1.f + LOG2PIf)) + log_det + fld;

    if (half == 0) {
        *reinterpret_cast<float4*>(P.out + grow * 8)     = a0;
        *reinterpret_cast<float4*>(P.out + grow * 8 + 4) = a1;
        P.out[Bq * 8 + grow]  = lp;
        P.out[Bq * 9 + grow]  = ent;
        P.out[Bq * 10 + grow] = amv[r * 12 + 8];
    }
}

extern "C" void kernel_launch(void* const* d_in, const int* in_sizes, int n_in,
                              void* d_out, int out_size) {
    (void)n_in; (void)out_size;
    Params P;
    P.x      = (const float*)d_in[0];
    P.action = (const float*)d_in[1];
    P.z_rpo  = (const float*)d_in[2];
    P.cW1    = (const float*)d_in[3];
    P.cb1    = (const float*)d_in[4];
    P.c_rms  = (const float*)d_in[5];
    P.cW2    = (const float*)d_in[6];
    P.cb2    = (const float*)d_in[7];
    P.cW3    = (const float*)d_in[8];
    P.cb3    = (const float*)d_in[9];
    P.aW1    = (const float*)d_in[10];
    P.ab1    = (const float*)d_in[11];
    P.aW2    = (const float*)d_in[12];
    P.ab2    = (const float*)d_in[13];
    P.mW     = (const float*)d_in[14];
    P.mb     = (const float*)d_in[15];
    P.tW1    = (const float*)d_in[16];
    P.tb1    = (const float*)d_in[17];
    P.t_rms1 = (const float*)d_in[18];
    P.tW2    = (const float*)d_in[19];
    P.tb2    = (const float*)d_in[20];
    P.t_rms2 = (const float*)d_in[21];
    P.hW     = (const float*)d_in[22];
    P.hb     = (const float*)d_in[23];
    P.fW1    = (const float*)d_in[24];
    P.fb1    = (const float*)d_in[25];
    P.fW2    = (const float*)d_in[26];
    P.fb2    = (const float*)d_in[27];
    P.out    = (float*)d_out;
    P.B      = in_sizes[0] / OBS;

    cudaFuncSetAttribute(fused_agent_tc,
                         cudaFuncAttributeMaxDynamicSharedMemorySize, SMEM_BYTES);
    fused_agent_tc<<<P.B / ROWS, THREADS, SMEM_BYTES>>>(P);
}

// round 8
// speedup vs baseline: 2.1298x; 1.0558x over previous
#include <cuda_runtime.h>
#include <cstdint>

#define THREADS 512
#define ROWS 128
#define OBS 128
#define H 64
#define AD 8
#define FH 32
#define NL 4

// ---------------- smem layout (floats) ----------------
#define XS_OFF    0                 // X A-frags: 8 mtiles * 16 kt * 128 = 16384
#define XS_F      16384
#define WBA_OFF   (XS_OFF + XS_F)   // weight buf A: 8192
#define WBA_F     8192
#define WBB_OFF   (WBA_OFF + WBA_F) // weight buf B: 6656
#define WBB_F     6656
#define ACTA_OFF  (WBB_OFF + WBB_F) // act A-frags: 8192
#define ACTA_F    8192
#define ACTB_OFF  (ACTA_OFF + ACTA_F)
#define ACTB_F    8192
#define AMV_OFF   (ACTB_OFF + ACTB_F) // [128][12]: mean 0..7, v at 8
#define AMV_F     (128*12)
#define LR_OFF    (AMV_OFF + AMV_F)   // [128][40]
#define LR_F      (128*40)
#define CST_OFF   (LR_OFF + LR_F)
// consts sublayout (relative to CST_OFF)
#define C_FCOND 0      // 4*4*32 = 512
#define C_FW2   512    // 4*32*8 = 2048
#define C_FB1   2560   // 128
#define C_FB2   2688   // 32
#define C_AB1   2720
#define C_AB2   2784
#define C_MB    2848   // 8
#define C_TB1   2856
#define C_TB2   2920
#define C_TR1   2984
#define C_TR2   3048
#define C_HBP   3112   // 40
#define C_CB1   3152
#define C_CB2   3216
#define C_CRMS  3280
#define C_VB    3344   // 8
#define CST_F   3352
#define RS_OFF  (CST_OFF + CST_F)   // rms partial sums [128][2]
#define RS_F    256
#define SMEM_F  (RS_OFF + RS_F)
#define SMEM_BYTES (SMEM_F * 4)

struct Params {
    const float *x, *action, *z_rpo;
    const float *cW1, *cb1, *c_rms, *cW2, *cb2, *cW3, *cb3;
    const float *aW1, *ab1, *aW2, *ab2, *mW, *mb;
    const float *tW1, *tb1, *t_rms1, *tW2, *tb2, *t_rms2, *hW, *hb;
    const float *fW1, *fb1, *fW2, *fb2;
    float *out;
    int B;
};

__device__ __forceinline__ float siluf(float v) { return v / (1.f + __expf(-v)); }

__device__ __forceinline__ float to_tf32(float f) {
    uint32_t o;
    asm("cvt.rna.tf32.f32 %0, %1;" : "=r"(o) : "f"(f));
    return __uint_as_float(o);
}

__device__ __forceinline__ void cpa4(float* smem_dst, const float* gsrc) {
    uint32_t s = (uint32_t)__cvta_generic_to_shared(smem_dst);
    asm volatile("cp.async.ca.shared.global [%0], [%1], 4;" :: "r"(s), "l"(gsrc));
}
__device__ __forceinline__ void cp_commit() { asm volatile("cp.async.commit_group;"); }
template<int N> __device__ __forceinline__ void cp_wait() {
    asm volatile("cp.async.wait_group %0;" :: "n"(N));
}

// ---- stage weight [K][NR] (row-major) into B-fragment layout, pad cols to NP ----
template<int K, int NP, int NR, int NT>
__device__ __forceinline__ void stage_B(float* dst, const float* g, int tid) {
    constexpr int TOT = K * NP;
    for (int i = tid; i < TOT; i += THREADS) {
        int k = i / NP, n = i % NP;
        int pos = (((k >> 3) * NT + (n >> 3)) * 32 + (n & 7) * 4 + (k & 3)) * 2 + ((k >> 2) & 1);
        if (NP == NR || n < NR) cpa4(dst + pos, g + k * NR + n);
        else dst[pos] = 0.f;
    }
}

__device__ __forceinline__ void cvtpass(float* w, int n, int tid) {
    for (int i = tid; i < n; i += THREADS) w[i] = to_tf32(w[i]);
}

// ---- tf32 mma m16n8k8 ----
__device__ __forceinline__ void mma8(float* c, uint32_t a0, uint32_t a1, uint32_t a2, uint32_t a3,
                                     uint32_t b0, uint32_t b1) {
    asm volatile("mma.sync.aligned.m16n8k8.row.col.f32.tf32.tf32.f32 "
                 "{%0,%1,%2,%3}, {%4,%5,%6,%7}, {%8,%9}, {%0,%1,%2,%3};"
                 : "+f"(c[0]), "+f"(c[1]), "+f"(c[2]), "+f"(c[3])
                 : "r"(a0), "r"(a1), "r"(a2), "r"(a3), "r"(b0), "r"(b1));
}

// warp computes NTloc n-tiles starting at ntBase (of NTtot total in B layout)
template<int KT, int NTtot, int NTloc>
__device__ __forceinline__ void gemm_frag(const float* __restrict__ A, const float* __restrict__ B,
                                          const float* __restrict__ bias,
                                          float (&acc)[NTloc][4], int lane, int t, int ntBase) {
#pragma unroll
    for (int nt = 0; nt < NTloc; ++nt) {
        float b0 = bias[(ntBase + nt) * 8 + 2 * t], b1 = bias[(ntBase + nt) * 8 + 2 * t + 1];
        acc[nt][0] = b0; acc[nt][1] = b1; acc[nt][2] = b0; acc[nt][3] = b1;
    }
#pragma unroll 4
    for (int kt = 0; kt < KT; ++kt) {
        float4 av = *reinterpret_cast<const float4*>(A + (kt * 32 + lane) * 4);
        uint32_t a0 = __float_as_uint(av.x), a1 = __float_as_uint(av.y);
        uint32_t a2 = __float_as_uint(av.z), a3 = __float_as_uint(av.w);
#pragma unroll
        for (int nt = 0; nt < NTloc; ++nt) {
            float2 bv = *reinterpret_cast<const float2*>(B + ((kt * NTtot + ntBase + nt) * 32 + lane) * 2);
            mma8(acc[nt], a0, a1, a2, a3, __float_as_uint(bv.x), __float_as_uint(bv.y));
        }
    }
}

// store one value into A-fragment layout (KT=8 buffers), mtile-indexed
__device__ __forceinline__ void store_act(float* buf, int mtile, int rl, int col, float v) {
    int kt = col >> 3, kin = col & 7;
    buf[(((mtile << 3) + kt) * 32 + ((rl & 7) << 2) + (kin & 3)) * 4 +
        ((rl >> 3) & 1) + (((kin >> 2) & 1) << 1)] = v;
}

// epilogue: silu -> tf32 -> act frags
template<int NTloc>
__device__ __forceinline__ void epi_silu(float (&acc)[NTloc][4], float* dst, int mtile,
                                         int g, int t, int ntBase) {
#pragma unroll
    for (int nt = 0; nt < NTloc; ++nt) {
        int c0 = (ntBase + nt) * 8 + 2 * t;
        store_act(dst, mtile, g,     c0,     to_tf32(siluf(acc[nt][0])));
        store_act(dst, mtile, g,     c0 + 1, to_tf32(siluf(acc[nt][1])));
        store_act(dst, mtile, g + 8, c0,     to_tf32(siluf(acc[nt][2])));
        store_act(dst, mtile, g + 8, c0 + 1, to_tf32(siluf(acc[nt][3])));
    }
}

// epilogue: silu + rms(w) across warp pair (smem exchange) -> tf32 -> act frags
// MUST be called by all threads of the block (contains __syncthreads).
template<int NTloc>
__device__ __forceinline__ void epi_silu_rms(float (&acc)[NTloc][4], float* dst, const float* w,
                                             int mtile, int g, int t, int nh, float* rsum) {
    float s_lo = 0.f, s_hi = 0.f;
#pragma unroll
    for (int nt = 0; nt < NTloc; ++nt) {
        acc[nt][0] = siluf(acc[nt][0]); acc[nt][1] = siluf(acc[nt][1]);
        acc[nt][2] = siluf(acc[nt][2]); acc[nt][3] = siluf(acc[nt][3]);
        s_lo += acc[nt][0] * acc[nt][0] + acc[nt][1] * acc[nt][1];
        s_hi += acc[nt][2] * acc[nt][2] + acc[nt][3] * acc[nt][3];
    }
    s_lo += __shfl_xor_sync(0xffffffffu, s_lo, 1);
    s_lo += __shfl_xor_sync(0xffffffffu, s_lo, 2);
    s_hi += __shfl_xor_sync(0xffffffffu, s_hi, 1);
    s_hi += __shfl_xor_sync(0xffffffffu, s_hi, 2);
    int rlo = mtile * 16 + g, rhi = rlo + 8;
    if (t == 0) { rsum[rlo * 2 + nh] = s_lo; rsum[rhi * 2 + nh] = s_hi; }
    __syncthreads();
    const float EPSF = 1.1920928955078125e-07f;
    float sc_lo = rsqrtf((rsum[rlo * 2] + rsum[rlo * 2 + 1]) * (1.f / 64.f) + EPSF);
    float sc_hi = rsqrtf((rsum[rhi * 2] + rsum[rhi * 2 + 1]) * (1.f / 64.f) + EPSF);
#pragma unroll
    for (int nt = 0; nt < NTloc; ++nt) {
        int c0 = (nh * NTloc + nt) * 8 + 2 * t;
        store_act(dst, mtile, g,     c0,     to_tf32(acc[nt][0] * sc_lo * w[c0]));
        store_act(dst, mtile, g,     c0 + 1, to_tf32(acc[nt][1] * sc_lo * w[c0 + 1]));
        store_act(dst, mtile, g + 8, c0,     to_tf32(acc[nt][2] * sc_hi * w[c0]));
        store_act(dst, mtile, g + 8, c0 + 1, to_tf32(acc[nt][3] * sc_hi * w[c0 + 1]));
    }
}

__global__ void __launch_bounds__(THREADS) fused_agent_tc(Params P) {
    extern __shared__ float sm[];
    float* xs   = sm + XS_OFF;
    float* wbA  = sm + WBA_OFF;
    float* wbB  = sm + WBB_OFF;
    float* actA = sm + ACTA_OFF;
    float* actB = sm + ACTB_OFF;
    float* amv  = sm + AMV_OFF;
    float* lr   = sm + LR_OFF;
    float* cst  = sm + CST_OFF;
    float* rsum = sm + RS_OFF;

    const int tid = threadIdx.x;
    const int warp = tid >> 5;       // 0..15
    const int lane = tid & 31;
    const int g = lane >> 2;
    const int t = lane & 3;
    const int mtile = warp >> 1;     // 0..7
    const int nh = warp & 1;         // n-half

    // ---- prefetch first two weight groups (async) ----
    stage_B<128, 64, 64, 8>(wbA, P.aW1, tid); cp_commit();                 // g1
    stage_B<64, 64, 64, 8>(wbB, P.aW2, tid);
    stage_B<64, 8, 8, 1>(wbB + 4096, P.mW, tid); cp_commit();              // g2

    // ---- stage X into A-fragment layout (tf32-rounded) ----
    {
        const float* gx = P.x + (size_t)blockIdx.x * ROWS * OBS;
        for (int i = tid; i < ROWS * OBS; i += THREADS) {
            int row = i >> 7, col = i & 127;
            float v = to_tf32(gx[i]);
            int mt = row >> 4, kt = col >> 3, kin = col & 7;
            xs[((mt * 16 + kt) * 32 + (row & 7) * 4 + (kin & 3)) * 4 +
               ((row >> 3) & 1) + (((kin >> 2) & 1) << 1)] = v;
        }
    }
    // ---- stage consts (plain) ----
    for (int i = tid; i < 512; i += THREADS)
        cst[C_FCOND + i] = P.fW1[((i >> 7) * 132 + ((i >> 5) & 3)) * 32 + (i & 31)];
    for (int i = tid; i < 2048; i += THREADS) cst[C_FW2 + i] = P.fW2[i];
    for (int i = tid; i < 128; i += THREADS) cst[C_FB1 + i] = P.fb1[i];
    if (tid < 32) cst[C_FB2 + tid] = P.fb2[tid];
    if (tid < 64) {
        cst[C_AB1 + tid] = P.ab1[tid]; cst[C_AB2 + tid] = P.ab2[tid];
        cst[C_TB1 + tid] = P.tb1[tid]; cst[C_TB2 + tid] = P.tb2[tid];
        cst[C_TR1 + tid] = P.t_rms1[tid]; cst[C_TR2 + tid] = P.t_rms2[tid];
        cst[C_CB1 + tid] = P.cb1[tid]; cst[C_CB2 + tid] = P.cb2[tid];
        cst[C_CRMS + tid] = P.c_rms[tid];
    }
    if (tid < 8) cst[C_MB + tid] = P.mb[tid];
    if (tid < 40) cst[C_HBP + tid] = (tid < 36) ? P.hb[tid] : 0.f;
    if (tid < 8) cst[C_VB + tid] = (tid == 0) ? P.cb3[0] : 0.f;

    cp_wait<1>(); __syncthreads();
    cvtpass(wbA, 8192, tid); __syncthreads();

    // ===== A1 = silu(X @ aW1 + ab1) =====
    {
        float acc[4][4];
        gemm_frag<16, 8, 4>(xs + mtile * 2048, wbA, cst + C_AB1, acc, lane, t, nh * 4);
        epi_silu<4>(acc, actA, mtile, g, t, nh * 4);
    }
    __syncthreads();
    stage_B<128, 64, 64, 8>(wbA, P.tW1, tid); cp_commit();                 // g3
    cp_wait<1>(); __syncthreads();
    cvtpass(wbB, 4608, tid); __syncthreads();

    // ===== A2 = silu(A1 @ aW2 + ab2) =====
    {
        float acc[4][4];
        gemm_frag<8, 8, 4>(actA + mtile * 1024, wbB, cst + C_AB2, acc, lane, t, nh * 4);
        epi_silu<4>(acc, actB, mtile, g, t, nh * 4);
    }
    __syncthreads();
    // ===== AM = A2 @ mW + mb (even warps) =====
    if (nh == 0) {
        float acc[1][4];
        gemm_frag<8, 1, 1>(actB + mtile * 1024, wbB + 4096, cst + C_MB, acc, lane, t, 0);
        int rlo = mtile * 16 + g, rhi = rlo + 8, c0 = 2 * t;
        amv[rlo * 12 + c0] = acc[0][0]; amv[rlo * 12 + c0 + 1] = acc[0][1];
        amv[rhi * 12 + c0] = acc[0][2]; amv[rhi * 12 + c0 + 1] = acc[0][3];
    }
    __syncthreads();
    stage_B<64, 64, 64, 8>(wbB, P.tW2, tid);
    stage_B<64, 40, 36, 5>(wbB + 4096, P.hW, tid); cp_commit();            // g4
    cp_wait<1>(); __syncthreads();
    cvtpass(wbA, 8192, tid); __syncthreads();

    // ===== T1 = rms(silu(X @ tW1 + tb1), t_rms1) =====
    {
        float acc[4][4];
        gemm_frag<16, 8, 4>(xs + mtile * 2048, wbA, cst + C_TB1, acc, lane, t, nh * 4);
        epi_silu_rms<4>(acc, actA, cst + C_TR1, mtile, g, t, nh, rsum);
    }
    __syncthreads();
    stage_B<128, 64, 64, 8>(wbA, P.cW1, tid); cp_commit();                 // g5
    cp_wait<1>(); __syncthreads();
    cvtpass(wbB, 6656, tid); __syncthreads();

    // ===== T2 = rms(silu(T1 @ tW2 + tb2), t_rms2) =====
    {
        float acc[4][4];
        gemm_frag<8, 8, 4>(actA + mtile * 1024, wbB, cst + C_TB2, acc, lane, t, nh * 4);
        epi_silu_rms<4>(acc, actB, cst + C_TR2, mtile, g, t, nh, rsum);
    }
    __syncthreads();
    // ===== Lraw = T2 @ hW + hb (N padded to 40; split 3/2) =====
    if (nh == 0) {
        float acc[3][4];
        gemm_frag<8, 5, 3>(actB + mtile * 1024, wbB + 4096, cst + C_HBP, acc, lane, t, 0);
        int rlo = mtile * 16 + g, rhi = rlo + 8;
#pragma unroll
        for (int nt = 0; nt < 3; ++nt) {
            int c0 = nt * 8 + 2 * t;
            lr[rlo * 40 + c0] = acc[nt][0]; lr[rlo * 40 + c0 + 1] = acc[nt][1];
            lr[rhi * 40 + c0] = acc[nt][2]; lr[rhi * 40 + c0 + 1] = acc[nt][3];
        }
    } else {
        float acc[2][4];
        gemm_frag<8, 5, 2>(actB + mtile * 1024, wbB + 4096, cst + C_HBP, acc, lane, t, 3);
        int rlo = mtile * 16 + g, rhi = rlo + 8;
#pragma unroll
        for (int nt = 0; nt < 2; ++nt) {
            int c0 = (3 + nt) * 8 + 2 * t;
            lr[rlo * 40 + c0] = acc[nt][0]; lr[rlo * 40 + c0 + 1] = acc[nt][1];
            lr[rhi * 40 + c0] = acc[nt][2]; lr[rhi * 40 + c0 + 1] = acc[nt][3];
        }
    }
    __syncthreads();
    stage_B<64, 64, 64, 8>(wbB, P.cW2, tid);
    stage_B<64, 8, 1, 1>(wbB + 4096, P.cW3, tid); cp_commit();             // g6
    cp_wait<1>(); __syncthreads();
    cvtpass(wbA, 8192, tid); __syncthreads();

    // ===== C1 = rms(silu(X @ cW1 + cb1), c_rms) =====
    {
        float acc[4][4];
        gemm_frag<16, 8, 4>(xs + mtile * 2048, wbA, cst + C_CB1, acc, lane, t, nh * 4);
        epi_silu_rms<4>(acc, actA, cst + C_CRMS, mtile, g, t, nh, rsum);
    }
    __syncthreads();
    stage_B<128, 32, 32, 4>(wbA,        P.fW1 + (size_t)(3 * 132 + 4) * 32, tid);
    stage_B<128, 32, 32, 4>(wbA + 4096, P.fW1 + (size_t)(2 * 132 + 4) * 32, tid); cp_commit(); // g7
    cp_wait<1>(); __syncthreads();
    cvtpass(wbB, 4608, tid); __syncthreads();

    // ===== C2 = silu(C1 @ cW2 + cb2) =====
    {
        float acc[4][4];
        gemm_frag<8, 8, 4>(actA + mtile * 1024, wbB, cst + C_CB2, acc, lane, t, nh * 4);
        epi_silu<4>(acc, actB, mtile, g, t, nh * 4);
    }
    __syncthreads();
    // ===== v = C2 @ cW3 + cb3 (even warps) =====
    if (nh == 0) {
        float acc[1][4];
        gemm_frag<8, 1, 1>(actB + mtile * 1024, wbB + 4096, cst + C_VB, acc, lane, t, 0);
        if (t == 0) {
            int rlo = mtile * 16 + g, rhi = rlo + 8;
            amv[rlo * 12 + 8] = acc[0][0];
            amv[rhi * 12 + 8] = acc[0][2];
        }
    }
    __syncthreads();
    stage_B<128, 32, 32, 4>(wbB, P.fW1 + (size_t)(1 * 132 + 4) * 32, tid); cp_commit(); // g8
    cp_wait<1>(); __syncthreads();
    cvtpass(wbA, 8192, tid); __syncthreads();

    // ===== U3 & U2 concurrent (warps 0-7: l=3 from wbA, warps 8-15: l=2 from wbA+4096)
    float* ub = actA;  // 4 layers * 128 rows * 32 cols, swizzled
    {
        const int l = 3 - (warp >> 3);
        const int mloc = warp & 7;
        const float* Bw = wbA + (warp >> 3) * 4096;
        float acc[4][4];
        gemm_frag<16, 4, 4>(xs + mloc * 2048, Bw, cst + C_FB1 + l * 32, acc, lane, t, 0);
        int rlo = mloc * 16 + g, rhi = rlo + 8;
#pragma unroll
        for (int nt = 0; nt < 4; ++nt) {
            int c0 = nt * 8 + 2 * t;
            ub[(l * 128 + rlo) * 32 + ((c0 + rlo) & 31)]     = acc[nt][0];
            ub[(l * 128 + rlo) * 32 + ((c0 + 1 + rlo) & 31)] = acc[nt][1];
            ub[(l * 128 + rhi) * 32 + ((c0 + rhi) & 31)]     = acc[nt][2];
            ub[(l * 128 + rhi) * 32 + ((c0 + 1 + rhi) & 31)] = acc[nt][3];
        }
    }
    __syncthreads();
    stage_B<128, 32, 32, 4>(wbA, P.fW1 + (size_t)(0 * 132 + 4) * 32, tid); cp_commit(); // g9
    cp_wait<1>(); __syncthreads();
    cvtpass(wbB, 4096, tid); __syncthreads();

    // ===== U1 (all warps, split-N) =====
    {
        const int l = 1;
        float acc[2][4];
        gemm_frag<16, 4, 2>(xs + mtile * 2048, wbB, cst + C_FB1 + l * 32, acc, lane, t, nh * 2);
        int rlo = mtile * 16 + g, rhi = rlo + 8;
#pragma unroll
        for (int nt = 0; nt < 2; ++nt) {
            int c0 = (nh * 2 + nt) * 8 + 2 * t;
            ub[(l * 128 + rlo) * 32 + ((c0 + rlo) & 31)]     = acc[nt][0];
            ub[(l * 128 + rlo) * 32 + ((c0 + 1 + rlo) & 31)] = acc[nt][1];
            ub[(l * 128 + rhi) * 32 + ((c0 + rhi) & 31)]     = acc[nt][2];
            ub[(l * 128 + rhi) * 32 + ((c0 + 1 + rhi) & 31)] = acc[nt][3];
        }
    }
    __syncthreads();
    cp_wait<0>(); __syncthreads();
    cvtpass(wbA, 4096, tid); __syncthreads();
    // ===== U0 (all warps, split-N) =====
    {
        const int l = 0;
        float acc[2][4];
        gemm_frag<16, 4, 2>(xs + mtile * 2048, wbA, cst + C_FB1 + l * 32, acc, lane, t, nh * 2);
        int rlo = mtile * 16 + g, rhi = rlo + 8;
#pragma unroll
        for (int nt = 0; nt < 2; ++nt) {
            int c0 = (nh * 2 + nt) * 8 + 2 * t;
            ub[(l * 128 + rlo) * 32 + ((c0 + rlo) & 31)]     = acc[nt][0];
            ub[(l * 128 + rlo) * 32 + ((c0 + 1 + rlo) & 31)] = acc[nt][1];
            ub[(l * 128 + rhi) * 32 + ((c0 + rhi) & 31)]     = acc[nt][2];
            ub[(l * 128 + rhi) * 32 + ((c0 + 1 + rhi) & 31)] = acc[nt][3];
        }
    }
    __syncthreads();

    // =================== SIMT tail: 4 threads per row ===================
    const int r = (warp << 3) + (lane >> 2);
    const int quarter = lane & 3;
    const size_t grow = (size_t)blockIdx.x * ROWS + r;
    const size_t Bq = (size_t)P.B;

    float4 a0 = *reinterpret_cast<const float4*>(P.action + grow * 8);
    float4 a1 = *reinterpret_cast<const float4*>(P.action + grow * 8 + 4);
    float4 z0 = *reinterpret_cast<const float4*>(P.z_rpo + grow * 8);
    float4 z1 = *reinterpret_cast<const float4*>(P.z_rpo + grow * 8 + 4);

    float x1v[4], x2v[4];
    x1v[0] = a0.x - amv[r * 12 + 0] - z0.x;
    x1v[1] = a0.y - amv[r * 12 + 1] - z0.y;
    x1v[2] = a0.z - amv[r * 12 + 2] - z0.z;
    x1v[3] = a0.w - amv[r * 12 + 3] - z0.w;
    x2v[0] = a1.x - amv[r * 12 + 4] - z1.x;
    x2v[1] = a1.y - amv[r * 12 + 5] - z1.y;
    x2v[2] = a1.z - amv[r * 12 + 6] - z1.z;
    x2v[3] = a1.w - amv[r * 12 + 7] - z1.w;

    const float* fcond = cst + C_FCOND;
    const float* fW2s  = cst + C_FW2;
    const float* fb2s  = cst + C_FB2;

    float fld = 0.f;
#pragma unroll
    for (int it = 0; it < NL; ++it) {
        const int i = NL - 1 - it;
        float* condp = (i % 2 == 0) ? x1v : x2v;
        float* yp    = (i % 2 == 0) ? x2v : x1v;
        float u[8];
#pragma unroll
        for (int jj = 0; jj < 8; ++jj) {
            int j = quarter * 8 + jj;
            u[jj] = ub[(i * 128 + r) * 32 + ((j + r) & 31)];
        }
#pragma unroll
        for (int c = 0; c < 4; ++c) {
            float cv = condp[c];
#pragma unroll
            for (int jj = 0; jj < 8; ++jj)
                u[jj] = fmaf(cv, fcond[(i * 4 + c) * 32 + quarter * 8 + jj], u[jj]);
        }
#pragma unroll
        for (int jj = 0; jj < 8; ++jj) u[jj] = siluf(u[jj]);
        float stp[8];
#pragma unroll
        for (int m = 0; m < 8; ++m) stp[m] = (quarter == 0) ? fb2s[i * 8 + m] : 0.f;
#pragma unroll
        for (int jj = 0; jj < 8; ++jj) {
            float uv = u[jj];
            const float* wrow = fW2s + (i * 32 + quarter * 8 + jj) * 8;
#pragma unroll
            for (int m = 0; m < 8; ++m) stp[m] = fmaf(uv, wrow[m], stp[m]);
        }
#pragma unroll
        for (int m = 0; m < 8; ++m) {
            stp[m] += __shfl_xor_sync(0xffffffffu, stp[m], 1);
            stp[m] += __shfl_xor_sync(0xffffffffu, stp[m], 2);
        }
#pragma unroll
        for (int m = 0; m < 4; ++m) {
            float s = 2.f * tanhf(stp[m]);
            fld += s;
            yp[m] = (yp[m] - stp[4 + m]) * __expf(-s);
        }
    }

    // triangular processing
    float Lm[36];
#pragma unroll
    for (int i = 0; i < 36; ++i) Lm[i] = lr[r * 40 + i];
    float log_det = 0.f;
#pragma unroll
    for (int i = 0; i < 8; ++i) {
        int d = i * (i + 3) / 2;
        float rv = Lm[d];
        float sp = fmaxf(rv, 0.f) + log1pf(__expf(-fabsf(rv)));
        Lm[d] = sp;
        log_det += __logf(sp);
    }
    float corr[8] = {x1v[0], x1v[1], x1v[2], x1v[3], x2v[0], x2v[1], x2v[2], x2v[3]};
    float zv[8];
#pragma unroll
    for (int i = 0; i < 8; ++i) {
        float acc = corr[i];
#pragma unroll
        for (int j = 0; j < 8; ++j)
            if (j < i) acc -= Lm[i * (i + 1) / 2 + j] * zv[j];
        zv[i] = acc / Lm[i * (i + 1) / 2 + i];
    }
    float mahal = 0.f;
#pragma unroll
    for (int i = 0; i < 8; ++i) mahal += zv[i] * zv[i];
    const float LOG2PIf = 1.8378770664093453f;
    float lp  = -0.5f * (8.f * LOG2PIf + mahal) - log_det - fld;
    float ent = 0.5f * (8.f * (1.f + LOG2PIf)) + log_det + fld;

    if (quarter == 0) {
        *reinterpret_cast<float4*>(P.out + grow * 8)     = a0;
        *reinterpret_cast<float4*>(P.out + grow * 8 + 4) = a1;
        P.out[Bq * 8 + grow]  = lp;
        P.out[Bq * 9 + grow]  = ent;
        P.out[Bq * 10 + grow] = amv[r * 12 + 8];
    }
}

extern "C" void kernel_launch(void* const* d_in, const int* in_sizes, int n_in,
                              void* d_out, int out_size) {
    (void)n_in; (void)out_size;
    Params P;
    P.x      = (const float*)d_in[0];
    P.action = (const float*)d_in[1];
    P.z_rpo  = (const float*)d_in[2];
    P.cW1    = (const float*)d_in[3];
    P.cb1    = (const float*)d_in[4];
    P.c_rms  = (const float*)d_in[5];
    P.cW2    = (const float*)d_in[6];
    P.cb2    = (const float*)d_in[7];
    P.cW3    = (const float*)d_in[8];
    P.cb3    = (const float*)d_in[9];
    P.aW1    = (const float*)d_in[10];
    P.ab1    = (const float*)d_in[11];
    P.aW2    = (const float*)d_in[12];
    P.ab2    = (const float*)d_in[13];
    P.mW     = (const float*)d_in[14];
    P.mb     = (const float*)d_in[15];
    P.tW1    = (const float*)d_in[16];
    P.tb1    = (const float*)d_in[17];
    P.t_rms1 = (const float*)d_in[18];
    P.tW2    = (const float*)d_in[19];
    P.tb2    = (const float*)d_in[20];
    P.t_rms2 = (const float*)d_in[21];
    P.hW     = (const float*)d_in[22];
    P.hb     = (const float*)d_in[23];
    P.fW1    = (const float*)d_in[24];
    P.fb1    = (const float*)d_in[25];
    P.fW2    = (const float*)d_in[26];
    P.fb2    = (const float*)d_in[27];
    P.out    = (float*)d_out;
    P.B      = in_sizes[0] / OBS;

    cudaFuncSetAttribute(fused_agent_tc,
                         cudaFuncAttributeMaxDynamicSharedMemorySize, SMEM_BYTES);
    fused_agent_tc<<<P.B / ROWS, THREADS, SMEM_BYTES>>>(P);
}

// round 13
// speedup vs baseline: 2.6423x; 1.2407x over previous
#include <cuda_runtime.h>
#include <cstdint>

#define THREADS 512
#define ROWS 128
#define OBS 128
#define H 64
#define AD 8
#define FH 32
#define NL 4

// ---------------- smem layout (floats) ----------------
#define XS_OFF    0
#define XS_F      16384
#define WBA_OFF   (XS_OFF + XS_F)
#define WBA_F     8192
#define WBB_OFF   (WBA_OFF + WBA_F)
#define WBB_F     6656
#define ACTA_OFF  (WBB_OFF + WBB_F)
#define ACTA_F    8192
#define ACTB_OFF  (ACTA_OFF + ACTA_F)
#define ACTB_F    8192
#define AMV_OFF   (ACTB_OFF + ACTB_F)
#define AMV_F     (128*12)
#define LR_OFF    (AMV_OFF + AMV_F)
#define LR_F      (128*40)
#define CST_OFF   (LR_OFF + LR_F)
#define C_FCOND 0
#define C_FW2   512
#define C_FB1   2560
#define C_FB2   2688
#define C_AB1   2720
#define C_AB2   2784
#define C_MB    2848
#define C_TB1   2856
#define C_TB2   2920
#define C_TR1   2984
#define C_TR2   3048
#define C_HBP   3112
#define C_CB1   3152
#define C_CB2   3216
#define C_CRMS  3280
#define C_VB    3344
#define CST_F   3352
#define RS_OFF  (CST_OFF + CST_F)
#define RS_F    256
#define SMEM_F  (RS_OFF + RS_F)
#define SMEM_BYTES (SMEM_F * 4)

// ---------------- weight scratch (pre-rounded, pre-layouted) ----------------
#define S_AW1 0
#define S_AW2 8192
#define S_MW  12288
#define S_TW1 12800
#define S_TW2 20992
#define S_HW  25088
#define S_CW1 27648
#define S_CW2 35840
#define S_CW3 39936
#define S_F3  40448
#define S_F2  44544
#define S_F1  48640
#define S_F0  52736
#define SCRATCH_F 56832

__device__ __align__(16) float g_wscratch[SCRATCH_F];

struct Params {
    const float *x, *action, *z_rpo;
    const float *cW1, *cb1, *c_rms, *cW2, *cb2, *cW3, *cb3;
    const float *aW1, *ab1, *aW2, *ab2, *mW, *mb;
    const float *tW1, *tb1, *t_rms1, *tW2, *tb2, *t_rms2, *hW, *hb;
    const float *fW1, *fb1, *fW2, *fb2;
    float *out;
    int B;
};

__device__ __forceinline__ float siluf(float v) { return v / (1.f + __expf(-v)); }

__device__ __forceinline__ float to_tf32(float f) {
    uint32_t o;
    asm("cvt.rna.tf32.f32 %0, %1;" : "=r"(o) : "f"(f));
    return __uint_as_float(o);
}

// ================= prep kernel: round + fragment-layout all weights once =================
__global__ void prep_weights(Params P) {
    struct GD { const float* s; int off, K, NP, NR, NT; };
    GD gd[13] = {
        {P.aW1,                              S_AW1, 128, 64, 64, 8},
        {P.aW2,                              S_AW2,  64, 64, 64, 8},
        {P.mW,                               S_MW,   64,  8,  8, 1},
        {P.tW1,                              S_TW1, 128, 64, 64, 8},
        {P.tW2,                              S_TW2,  64, 64, 64, 8},
        {P.hW,                               S_HW,   64, 40, 36, 5},
        {P.cW1,                              S_CW1, 128, 64, 64, 8},
        {P.cW2,                              S_CW2,  64, 64, 64, 8},
        {P.cW3,                              S_CW3,  64,  8,  1, 1},
        {P.fW1 + (size_t)(3 * 132 + 4) * 32, S_F3,  128, 32, 32, 4},
        {P.fW1 + (size_t)(2 * 132 + 4) * 32, S_F2,  128, 32, 32, 4},
        {P.fW1 + (size_t)(1 * 132 + 4) * 32, S_F1,  128, 32, 32, 4},
        {P.fW1 + (size_t)(0 * 132 + 4) * 32, S_F0,  128, 32, 32, 4},
    };
    int idx = blockIdx.x * blockDim.x + threadIdx.x;
    for (int gi = 0; gi < 13; ++gi) {
        int tot = gd[gi].K * gd[gi].NP;
        if (idx < tot) {
            int k = idx / gd[gi].NP, n = idx % gd[gi].NP;
            int pos = (((k >> 3) * gd[gi].NT + (n >> 3)) * 32 + (n & 7) * 4 + (k & 3)) * 2 + ((k >> 2) & 1);
            float v = (n < gd[gi].NR) ? to_tf32(gd[gi].s[(size_t)k * gd[gi].NR + n]) : 0.f;
            g_wscratch[gd[gi].off + pos] = v;
            return;
        }
        idx -= tot;
    }
}

// ---- contiguous 16B async copy from scratch ----
__device__ __forceinline__ void stage_lin(float* dst, const float* src, int nfloats, int tid) {
    for (int i = tid * 4; i < nfloats; i += THREADS * 4) {
        uint32_t s = (uint32_t)__cvta_generic_to_shared(dst + i);
        asm volatile("cp.async.cg.shared.global [%0], [%1], 16;" :: "r"(s), "l"(src + i));
    }
}
__device__ __forceinline__ void cp_commit() { asm volatile("cp.async.commit_group;"); }
template<int N> __device__ __forceinline__ void cp_wait() {
    asm volatile("cp.async.wait_group %0;" :: "n"(N));
}

// ---- tf32 mma m16n8k8 ----
__device__ __forceinline__ void mma8(float* c, uint32_t a0, uint32_t a1, uint32_t a2, uint32_t a3,
                                     uint32_t b0, uint32_t b1) {
    asm volatile("mma.sync.aligned.m16n8k8.row.col.f32.tf32.tf32.f32 "
                 "{%0,%1,%2,%3}, {%4,%5,%6,%7}, {%8,%9}, {%0,%1,%2,%3};"
                 : "+f"(c[0]), "+f"(c[1]), "+f"(c[2]), "+f"(c[3])
                 : "r"(a0), "r"(a1), "r"(a2), "r"(a3), "r"(b0), "r"(b1));
}

template<int KT, int NTtot, int NTloc>
__device__ __forceinline__ void gemm_frag(const float* __restrict__ A, const float* __restrict__ B,
                                          const float* __restrict__ bias,
                                          float (&acc)[NTloc][4], int lane, int t, int ntBase) {
#pragma unroll
    for (int nt = 0; nt < NTloc; ++nt) {
        float b0 = bias[(ntBase + nt) * 8 + 2 * t], b1 = bias[(ntBase + nt) * 8 + 2 * t + 1];
        acc[nt][0] = b0; acc[nt][1] = b1; acc[nt][2] = b0; acc[nt][3] = b1;
    }
#pragma unroll 4
    for (int kt = 0; kt < KT; ++kt) {
        float4 av = *reinterpret_cast<const float4*>(A + (kt * 32 + lane) * 4);
        uint32_t a0 = __float_as_uint(av.x), a1 = __float_as_uint(av.y);
        uint32_t a2 = __float_as_uint(av.z), a3 = __float_as_uint(av.w);
#pragma unroll
        for (int nt = 0; nt < NTloc; ++nt) {
            float2 bv = *reinterpret_cast<const float2*>(B + ((kt * NTtot + ntBase + nt) * 32 + lane) * 2);
            mma8(acc[nt], a0, a1, a2, a3, __float_as_uint(bv.x), __float_as_uint(bv.y));
        }
    }
}

__device__ __forceinline__ void store_act(float* buf, int mtile, int rl, int col, float v) {
    int kt = col >> 3, kin = col & 7;
    buf[(((mtile << 3) + kt) * 32 + ((rl & 7) << 2) + (kin & 3)) * 4 +
        ((rl >> 3) & 1) + (((kin >> 2) & 1) << 1)] = v;
}

template<int NTloc>
__device__ __forceinline__ void epi_silu(float (&acc)[NTloc][4], float* dst, int mtile,
                                         int g, int t, int ntBase) {
#pragma unroll
    for (int nt = 0; nt < NTloc; ++nt) {
        int c0 = (ntBase + nt) * 8 + 2 * t;
        store_act(dst, mtile, g,     c0,     to_tf32(siluf(acc[nt][0])));
        store_act(dst, mtile, g,     c0 + 1, to_tf32(siluf(acc[nt][1])));
        store_act(dst, mtile, g + 8, c0,     to_tf32(siluf(acc[nt][2])));
        store_act(dst, mtile, g + 8, c0 + 1, to_tf32(siluf(acc[nt][3])));
    }
}

template<int NTloc>
__device__ __forceinline__ void epi_silu_rms(float (&acc)[NTloc][4], float* dst, const float* w,
                                             int mtile, int g, int t, int nh, float* rsum) {
    float s_lo = 0.f, s_hi = 0.f;
#pragma unroll
    for (int nt = 0; nt < NTloc; ++nt) {
        acc[nt][0] = siluf(acc[nt][0]); acc[nt][1] = siluf(acc[nt][1]);
        acc[nt][2] = siluf(acc[nt][2]); acc[nt][3] = siluf(acc[nt][3]);
        s_lo += acc[nt][0] * acc[nt][0] + acc[nt][1] * acc[nt][1];
        s_hi += acc[nt][2] * acc[nt][2] + acc[nt][3] * acc[nt][3];
    }
    s_lo += __shfl_xor_sync(0xffffffffu, s_lo, 1);
    s_lo += __shfl_xor_sync(0xffffffffu, s_lo, 2);
    s_hi += __shfl_xor_sync(0xffffffffu, s_hi, 1);
    s_hi += __shfl_xor_sync(0xffffffffu, s_hi, 2);
    int rlo = mtile * 16 + g, rhi = rlo + 8;
    if (t == 0) { rsum[rlo * 2 + nh] = s_lo; rsum[rhi * 2 + nh] = s_hi; }
    __syncthreads();
    const float EPSF = 1.1920928955078125e-07f;
    float sc_lo = rsqrtf((rsum[rlo * 2] + rsum[rlo * 2 + 1]) * (1.f / 64.f) + EPSF);
    float sc_hi = rsqrtf((rsum[rhi * 2] + rsum[rhi * 2 + 1]) * (1.f / 64.f) + EPSF);
#pragma unroll
    for (int nt = 0; nt < NTloc; ++nt) {
        int c0 = (nh * NTloc + nt) * 8 + 2 * t;
        store_act(dst, mtile, g,     c0,     to_tf32(acc[nt][0] * sc_lo * w[c0]));
        store_act(dst, mtile, g,     c0 + 1, to_tf32(acc[nt][1] * sc_lo * w[c0 + 1]));
        store_act(dst, mtile, g + 8, c0,     to_tf32(acc[nt][2] * sc_hi * w[c0]));
        store_act(dst, mtile, g + 8, c0 + 1, to_tf32(acc[nt][3] * sc_hi * w[c0 + 1]));
    }
}

__global__ void __launch_bounds__(THREADS) fused_agent_tc(Params P) {
    extern __shared__ float sm[];
    float* xs   = sm + XS_OFF;
    float* wbA  = sm + WBA_OFF;
    float* wbB  = sm + WBB_OFF;
    float* actA = sm + ACTA_OFF;
    float* actB = sm + ACTB_OFF;
    float* amv  = sm + AMV_OFF;
    float* lr   = sm + LR_OFF;
    float* cst  = sm + CST_OFF;
    float* rsum = sm + RS_OFF;

    const int tid = threadIdx.x;
    const int warp = tid >> 5;
    const int lane = tid & 31;
    const int g = lane >> 2;
    const int t = lane & 3;
    const int mtile = warp >> 1;
    const int nh = warp & 1;

    // ---- prefetch first two weight groups (pure contiguous 16B copies) ----
    stage_lin(wbA, g_wscratch + S_AW1, 8192, tid); cp_commit();            // g1
    stage_lin(wbB, g_wscratch + S_AW2, 4608, tid); cp_commit();            // g2 (aW2+mW)

    // ---- stage X into A-fragment layout (tf32-rounded, float4 loads) ----
    {
        const float* gx = P.x + (size_t)blockIdx.x * ROWS * OBS;
        for (int i = tid * 4; i < ROWS * OBS; i += THREADS * 4) {
            float4 v4 = *reinterpret_cast<const float4*>(gx + i);
            int row = i >> 7, col = i & 127;
            int mt = row >> 4, kt = col >> 3;
            float vv[4] = {v4.x, v4.y, v4.z, v4.w};
#pragma unroll
            for (int e = 0; e < 4; ++e) {
                int kin = (col + e) & 7;
                xs[((mt * 16 + kt) * 32 + (row & 7) * 4 + (kin & 3)) * 4 +
                   ((row >> 3) & 1) + (((kin >> 2) & 1) << 1)] = to_tf32(vv[e]);
            }
        }
    }
    // ---- stage consts ----
    for (int i = tid; i < 512; i += THREADS)
        cst[C_FCOND + i] = P.fW1[((i >> 7) * 132 + ((i >> 5) & 3)) * 32 + (i & 31)];
    for (int i = tid; i < 2048; i += THREADS) cst[C_FW2 + i] = P.fW2[i];
    for (int i = tid; i < 128; i += THREADS) cst[C_FB1 + i] = P.fb1[i];
    if (tid < 32) cst[C_FB2 + tid] = P.fb2[tid];
    if (tid < 64) {
        cst[C_AB1 + tid] = P.ab1[tid]; cst[C_AB2 + tid] = P.ab2[tid];
        cst[C_TB1 + tid] = P.tb1[tid]; cst[C_TB2 + tid] = P.tb2[tid];
        cst[C_TR1 + tid] = P.t_rms1[tid]; cst[C_TR2 + tid] = P.t_rms2[tid];
        cst[C_CB1 + tid] = P.cb1[tid]; cst[C_CB2 + tid] = P.cb2[tid];
        cst[C_CRMS + tid] = P.c_rms[tid];
    }
    if (tid < 8) cst[C_MB + tid] = P.mb[tid];
    if (tid < 40) cst[C_HBP + tid] = (tid < 36) ? P.hb[tid] : 0.f;
    if (tid < 8) cst[C_VB + tid] = (tid == 0) ? P.cb3[0] : 0.f;

    cp_wait<1>(); __syncthreads();   // g1 (wbA=aW1) ready

    // ===== A1 = silu(X @ aW1 + ab1) =====
    {
        float acc[4][4];
        gemm_frag<16, 8, 4>(xs + mtile * 2048, wbA, cst + C_AB1, acc, lane, t, nh * 4);
        epi_silu<4>(acc, actA, mtile, g, t, nh * 4);
    }
    __syncthreads();                 // wbA consumed, actA written
    stage_lin(wbA, g_wscratch + S_TW1, 8192, tid); cp_commit();            // g3
    cp_wait<1>(); __syncthreads();   // g2 (wbB) ready

    // ===== A2 = silu(A1 @ aW2 + ab2) =====
    {
        float acc[4][4];
        gemm_frag<8, 8, 4>(actA + mtile * 1024, wbB, cst + C_AB2, acc, lane, t, nh * 4);
        epi_silu<4>(acc, actB, mtile, g, t, nh * 4);
    }
    __syncthreads();                 // actB written
    // ===== AM = A2 @ mW + mb (even warps) =====
    if (nh == 0) {
        float acc[1][4];
        gemm_frag<8, 1, 1>(actB + mtile * 1024, wbB + 4096, cst + C_MB, acc, lane, t, 0);
        int rlo = mtile * 16 + g, rhi = rlo + 8, c0 = 2 * t;
        amv[rlo * 12 + c0] = acc[0][0]; amv[rlo * 12 + c0 + 1] = acc[0][1];
        amv[rhi * 12 + c0] = acc[0][2]; amv[rhi * 12 + c0 + 1] = acc[0][3];
    }
    __syncthreads();                 // wbB consumed
    stage_lin(wbB, g_wscratch + S_TW2, 6656, tid); cp_commit();            // g4 (tW2+hW)
    cp_wait<1>(); __syncthreads();   // g3 (wbA=tW1) ready

    // ===== T1 = rms(silu(X @ tW1 + tb1), t_rms1) =====
    {
        float acc[4][4];
        gemm_frag<16, 8, 4>(xs + mtile * 2048, wbA, cst + C_TB1, acc, lane, t, nh * 4);
        epi_silu_rms<4>(acc, actA, cst + C_TR1, mtile, g, t, nh, rsum);
    }
    __syncthreads();                 // wbA consumed
    stage_lin(wbA, g_wscratch + S_CW1, 8192, tid); cp_commit();            // g5
    cp_wait<1>(); __syncthreads();   // g4 (wbB) ready

    // ===== T2 = rms(silu(T1 @ tW2 + tb2), t_rms2) =====
    {
        float acc[4][4];
        gemm_frag<8, 8, 4>(actA + mtile * 1024, wbB, cst + C_TB2, acc, lane, t, nh * 4);
        epi_silu_rms<4>(acc, actB, cst + C_TR2, mtile, g, t, nh, rsum);
    }
    __syncthreads();                 // actB written
    // ===== Lraw = T2 @ hW + hb (split 3/2) =====
    if (nh == 0) {
        float acc[3][4];
        gemm_frag<8, 5, 3>(actB + mtile * 1024, wbB + 4096, cst + C_HBP, acc, lane, t, 0);
        int rlo = mtile * 16 + g, rhi = rlo + 8;
#pragma unroll
        for (int nt = 0; nt < 3; ++nt) {
            int c0 = nt * 8 + 2 * t;
            lr[rlo * 40 + c0] = acc[nt][0]; lr[rlo * 40 + c0 + 1] = acc[nt][1];
            lr[rhi * 40 + c0] = acc[nt][2]; lr[rhi * 40 + c0 + 1] = acc[nt][3];
        }
    } else {
        float acc[2][4];
        gemm_frag<8, 5, 2>(actB + mtile * 1024, wbB + 4096, cst + C_HBP, acc, lane, t, 3);
        int rlo = mtile * 16 + g, rhi = rlo + 8;
#pragma unroll
        for (int nt = 0; nt < 2; ++nt) {
            int c0 = (3 + nt) * 8 + 2 * t;
            lr[rlo * 40 + c0] = acc[nt][0]; lr[rlo * 40 + c0 + 1] = acc[nt][1];
            lr[rhi * 40 + c0] = acc[nt][2]; lr[rhi * 40 + c0 + 1] = acc[nt][3];
        }
    }
    __syncthreads();                 // wbB consumed
    stage_lin(wbB, g_wscratch + S_CW2, 4608, tid); cp_commit();            // g6 (cW2+cW3)
    cp_wait<1>(); __syncthreads();   // g5 (wbA=cW1) ready

    // ===== C1 = rms(silu(X @ cW1 + cb1), c_rms) =====
    {
        float acc[4][4];
        gemm_frag<16, 8, 4>(xs + mtile * 2048, wbA, cst + C_CB1, acc, lane, t, nh * 4);
        epi_silu_rms<4>(acc, actA, cst + C_CRMS, mtile, g, t, nh, rsum);
    }
    __syncthreads();                 // wbA consumed
    stage_lin(wbA, g_wscratch + S_F3, 8192, tid); cp_commit();             // g7 (fW1 l3,l2)
    cp_wait<1>(); __syncthreads();   // g6 (wbB) ready

    // ===== C2 = silu(C1 @ cW2 + cb2) =====
    {
        float acc[4][4];
        gemm_frag<8, 8, 4>(actA + mtile * 1024, wbB, cst + C_CB2, acc, lane, t, nh * 4);
        epi_silu<4>(acc, actB, mtile, g, t, nh * 4);
    }
    __syncthreads();                 // actB written
    // ===== v = C2 @ cW3 + cb3 (even warps) =====
    if (nh == 0) {
        float acc[1][4];
        gemm_frag<8, 1, 1>(actB + mtile * 1024, wbB + 4096, cst + C_VB, acc, lane, t, 0);
        if (t == 0) {
            int rlo = mtile * 16 + g, rhi = rlo + 8;
            amv[rlo * 12 + 8] = acc[0][0];
            amv[rhi * 12 + 8] = acc[0][2];
        }
    }
    __syncthreads();                 // wbB consumed, actA free
    stage_lin(wbB, g_wscratch + S_F1, 4096, tid); cp_commit();             // g8 (fW1 l1)
    cp_wait<1>(); __syncthreads();   // g7 (wbA) ready

    // ===== U3 & U2 concurrent =====
    float* ub = actA;
    {
        const int l = 3 - (warp >> 3);
        const int mloc = warp & 7;
        const float* Bw = wbA + (warp >> 3) * 4096;
        float acc[4][4];
        gemm_frag<16, 4, 4>(xs + mloc * 2048, Bw, cst + C_FB1 + l * 32, acc, lane, t, 0);
        int rlo = mloc * 16 + g, rhi = rlo + 8;
#pragma unroll
        for (int nt = 0; nt < 4; ++nt) {
            int c0 = nt * 8 + 2 * t;
            ub[(l * 128 + rlo) * 32 + ((c0 + rlo) & 31)]     = acc[nt][0];
            ub[(l * 128 + rlo) * 32 + ((c0 + 1 + rlo) & 31)] = acc[nt][1];
            ub[(l * 128 + rhi) * 32 + ((c0 + rhi) & 31)]     = acc[nt][2];
            ub[(l * 128 + rhi) * 32 + ((c0 + 1 + rhi) & 31)] = acc[nt][3];
        }
    }
    __syncthreads();                 // wbA consumed
    stage_lin(wbA, g_wscratch + S_F0, 4096, tid); cp_commit();             // g9 (fW1 l0)
    cp_wait<1>(); __syncthreads();   // g8 (wbB) ready

    // ===== U1 =====
    {
        const int l = 1;
        float acc[2][4];
        gemm_frag<16, 4, 2>(xs + mtile * 2048, wbB, cst + C_FB1 + l * 32, acc, lane, t, nh * 2);
        int rlo = mtile * 16 + g, rhi = rlo + 8;
#pragma unroll
        for (int nt = 0; nt < 2; ++nt) {
            int c0 = (nh * 2 + nt) * 8 + 2 * t;
            ub[(l * 128 + rlo) * 32 + ((c0 + rlo) & 31)]     = acc[nt][0];
            ub[(l * 128 + rlo) * 32 + ((c0 + 1 + rlo) & 31)] = acc[nt][1];
            ub[(l * 128 + rhi) * 32 + ((c0 + rhi) & 31)]     = acc[nt][2];
            ub[(l * 128 + rhi) * 32 + ((c0 + 1 + rhi) & 31)] = acc[nt][3];
        }
    }
    cp_wait<0>(); __syncthreads();   // g9 (wbA) ready
    // ===== U0 =====
    {
        const int l = 0;
        float acc[2][4];
        gemm_frag<16, 4, 2>(xs + mtile * 2048, wbA, cst + C_FB1 + l * 32, acc, lane, t, nh * 2);
        int rlo = mtile * 16 + g, rhi = rlo + 8;
#pragma unroll
        for (int nt = 0; nt < 2; ++nt) {
            int c0 = (nh * 2 + nt) * 8 + 2 * t;
            ub[(l * 128 + rlo) * 32 + ((c0 + rlo) & 31)]     = acc[nt][0];
            ub[(l * 128 + rlo) * 32 + ((c0 + 1 + rlo) & 31)] = acc[nt][1];
            ub[(l * 128 + rhi) * 32 + ((c0 + rhi) & 31)]     = acc[nt][2];
            ub[(l * 128 + rhi) * 32 + ((c0 + 1 + rhi) & 31)] = acc[nt][3];
        }
    }
    __syncthreads();

    // =================== SIMT tail: 4 threads per row ===================
    const int r = (warp << 3) + (lane >> 2);
    const int quarter = lane & 3;
    const size_t grow = (size_t)blockIdx.x * ROWS + r;
    const size_t Bq = (size_t)P.B;

    float4 a0 = *reinterpret_cast<const float4*>(P.action + grow * 8);
    float4 a1 = *reinterpret_cast<const float4*>(P.action + grow * 8 + 4);
    float4 z0 = *reinterpret_cast<const float4*>(P.z_rpo + grow * 8);
    float4 z1 = *reinterpret_cast<const float4*>(P.z_rpo + grow * 8 + 4);

    float x1v[4], x2v[4];
    x1v[0] = a0.x - amv[r * 12 + 0] - z0.x;
    x1v[1] = a0.y - amv[r * 12 + 1] - z0.y;
    x1v[2] = a0.z - amv[r * 12 + 2] - z0.z;
    x1v[3] = a0.w - amv[r * 12 + 3] - z0.w;
    x2v[0] = a1.x - amv[r * 12 + 4] - z1.x;
    x2v[1] = a1.y - amv[r * 12 + 5] - z1.y;
    x2v[2] = a1.z - amv[r * 12 + 6] - z1.z;
    x2v[3] = a1.w - amv[r * 12 + 7] - z1.w;

    const float* fcond = cst + C_FCOND;
    const float* fW2s  = cst + C_FW2;
    const float* fb2s  = cst + C_FB2;

    float fld = 0.f;
#pragma unroll
    for (int it = 0; it < NL; ++it) {
        const int i = NL - 1 - it;
        float* condp = (i % 2 == 0) ? x1v : x2v;
        float* yp    = (i % 2 == 0) ? x2v : x1v;
        float u[8];
#pragma unroll
        for (int jj = 0; jj < 8; ++jj) {
            int j = quarter * 8 + jj;
            u[jj] = ub[(i * 128 + r) * 32 + ((j + r) & 31)];
        }
#pragma unroll
        for (int c = 0; c < 4; ++c) {
            float cv = condp[c];
#pragma unroll
            for (int jj = 0; jj < 8; ++jj)
                u[jj] = fmaf(cv, fcond[(i * 4 + c) * 32 + quarter * 8 + jj], u[jj]);
        }
#pragma unroll
        for (int jj = 0; jj < 8; ++jj) u[jj] = siluf(u[jj]);
        float stp[8];
#pragma unroll
        for (int m = 0; m < 8; ++m) stp[m] = (quarter == 0) ? fb2s[i * 8 + m] : 0.f;
#pragma unroll
        for (int jj = 0; jj < 8; ++jj) {
            float uv = u[jj];
            const float* wrow = fW2s + (i * 32 + quarter * 8 + jj) * 8;
#pragma unroll
            for (int m = 0; m < 8; ++m) stp[m] = fmaf(uv, wrow[m], stp[m]);
        }
#pragma unroll
        for (int m = 0; m < 8; ++m) {
            stp[m] += __shfl_xor_sync(0xffffffffu, stp[m], 1);
            stp[m] += __shfl_xor_sync(0xffffffffu, stp[m], 2);
        }
#pragma unroll
        for (int m = 0; m < 4; ++m) {
            float s = 2.f * tanhf(stp[m]);
            fld += s;
            yp[m] = (yp[m] - stp[4 + m]) * __expf(-s);
        }
    }

    float Lm[36];
#pragma unroll
    for (int i = 0; i < 36; ++i) Lm[i] = lr[r * 40 + i];
    float log_det = 0.f;
#pragma unroll
    for (int i = 0; i < 8; ++i) {
        int d = i * (i + 3) / 2;
        float rv = Lm[d];
        float sp = fmaxf(rv, 0.f) + log1pf(__expf(-fabsf(rv)));
        Lm[d] = sp;
        log_det += __logf(sp);
    }
    float corr[8] = {x1v[0], x1v[1], x1v[2], x1v[3], x2v[0], x2v[1], x2v[2], x2v[3]};
    float zv[8];
#pragma unroll
    for (int i = 0; i < 8; ++i) {
        float acc = corr[i];
#pragma unroll
        for (int j = 0; j < 8; ++j)
            if (j < i) acc -= Lm[i * (i + 1) / 2 + j] * zv[j];
        zv[i] = acc / Lm[i * (i + 1) / 2 + i];
    }
    float mahal = 0.f;
#pragma unroll
    for (int i = 0; i < 8; ++i) mahal += zv[i] * zv[i];
    const float LOG2PIf = 1.8378770664093453f;
    float lp  = -0.5f * (8.f * LOG2PIf + mahal) - log_det - fld;
    float ent = 0.5f * (8.f * (1.f + LOG2PIf)) + log_det + fld;

    if (quarter == 0) {
        *reinterpret_cast<float4*>(P.out + grow * 8)     = a0;
        *reinterpret_cast<float4*>(P.out + grow * 8 + 4) = a1;
        P.out[Bq * 8 + grow]  = lp;
        P.out[Bq * 9 + grow]  = ent;
        P.out[Bq * 10 + grow] = amv[r * 12 + 8];
    }
}

extern "C" void kernel_launch(void* const* d_in, const int* in_sizes, int n_in,
                              void* d_out, int out_size) {
    (void)n_in; (void)out_size;
    Params P;
    P.x      = (const float*)d_in[0];
    P.action = (const float*)d_in[1];
    P.z_rpo  = (const float*)d_in[2];
    P.cW1    = (const float*)d_in[3];
    P.cb1    = (const float*)d_in[4];
    P.c_rms  = (const float*)d_in[5];
    P.cW2    = (const float*)d_in[6];
    P.cb2    = (const float*)d_in[7];
    P.cW3    = (const float*)d_in[8];
    P.cb3    = (const float*)d_in[9];
    P.aW1    = (const float*)d_in[10];
    P.ab1    = (const float*)d_in[11];
    P.aW2    = (const float*)d_in[12];
    P.ab2    = (const float*)d_in[13];
    P.mW     = (const float*)d_in[14];
    P.mb     = (const float*)d_in[15];
    P.tW1    = (const float*)d_in[16];
    P.tb1    = (const float*)d_in[17];
    P.t_rms1 = (const float*)d_in[18];
    P.tW2    = (const float*)d_in[19];
    P.tb2    = (const float*)d_in[20];
    P.t_rms2 = (const float*)d_in[21];
    P.hW     = (const float*)d_in[22];
    P.hb     = (const float*)d_in[23];
    P.fW1    = (const float*)d_in[24];
    P.fb1    = (const float*)d_in[25];
    P.fW2    = (const float*)d_in[26];
    P.fb2    = (const float*)d_in[27];
    P.out    = (float*)d_out;
    P.B      = in_sizes[0] / OBS;

    prep_weights<<<(SCRATCH_F + 255) / 256, 256>>>(P);
    cudaFuncSetAttribute(fused_agent_tc,
                         cudaFuncAttributeMaxDynamicSharedMemorySize, SMEM_BYTES);
    fused_agent_tc<<<P.B / ROWS, THREADS, SMEM_BYTES>>>(P);
}

// round 15
// speedup vs baseline: 2.9446x; 1.1144x over previous
#include <cuda_runtime.h>
#include <cstdint>

#define THREADS 512
#define ROWS 128
#define OBS 128
#define H 64
#define AD 8
#define FH 32
#define NL 4

// ---------------- smem layout (floats) ----------------
#define XS_OFF    0
#define XS_F      16384
#define WBA_OFF   (XS_OFF + XS_F)
#define WBA_F     8192
#define WBB_OFF   (WBA_OFF + WBA_F)
#define WBB_F     6656
#define ACTA_OFF  (WBB_OFF + WBB_F)
#define ACTA_F    8192
#define ACTB_OFF  (ACTA_OFF + ACTA_F)
#define ACTB_F    8192
#define AMV_OFF   (ACTB_OFF + ACTB_F)
#define AMV_F     (128*12)
#define LR_OFF    (AMV_OFF + AMV_F)
#define LR_F      (128*40)
#define CST_OFF   (LR_OFF + LR_F)
#define C_FCOND 0
#define C_FW2   512
#define C_FB1   2560
#define C_FB2   2688
#define C_AB1   2720
#define C_AB2   2784
#define C_MB    2848
#define C_TB1   2856
#define C_TB2   2920
#define C_TR1   2984
#define C_TR2   3048
#define C_HBP   3112
#define C_CB1   3152
#define C_CB2   3216
#define C_CRMS  3280
#define C_VB    3344
#define CST_F   3352
#define RS_OFF  (CST_OFF + CST_F)
#define RS_F    256
#define SMEM_F  (RS_OFF + RS_F)
#define SMEM_BYTES (SMEM_F * 4)

// ---------------- weight scratch (pre-rounded, pre-layouted) ----------------
#define S_AW1 0
#define S_AW2 8192
#define S_MW  12288
#define S_TW1 12800
#define S_TW2 20992
#define S_HW  25088
#define S_CW1 27648
#define S_CW2 35840
#define S_CW3 39936
#define S_F3  40448
#define S_F2  44544
#define S_F1  48640
#define S_F0  52736
#define SCRATCH_F 56832

__device__ __align__(16) float g_wscratch[SCRATCH_F];

struct Params {
    const float *x, *action, *z_rpo;
    const float *cW1, *cb1, *c_rms, *cW2, *cb2, *cW3, *cb3;
    const float *aW1, *ab1, *aW2, *ab2, *mW, *mb;
    const float *tW1, *tb1, *t_rms1, *tW2, *tb2, *t_rms2, *hW, *hb;
    const float *fW1, *fb1, *fW2, *fb2;
    float *out;
    int B;
};

__device__ __forceinline__ float siluf(float v) {
    return __fdividef(v, 1.f + __expf(-v));
}

__device__ __forceinline__ float to_tf32(float f) {
    uint32_t o;
    asm("cvt.rna.tf32.f32 %0, %1;" : "=r"(o) : "f"(f));
    return __uint_as_float(o);
}

// ================= prep kernel: round + fragment-layout all weights once =================
// paired=1: two adjacent n-tiles interleaved so one float4 per lane feeds two mmas.
__global__ void prep_weights(Params P) {
    struct GD { const float* s; int off, K, NP, NR, NT, paired; };
    GD gd[13] = {
        {P.aW1,                              S_AW1, 128, 64, 64, 8, 1},
        {P.aW2,                              S_AW2,  64, 64, 64, 8, 1},
        {P.mW,                               S_MW,   64,  8,  8, 1, 0},
        {P.tW1,                              S_TW1, 128, 64, 64, 8, 1},
        {P.tW2,                              S_TW2,  64, 64, 64, 8, 1},
        {P.hW,                               S_HW,   64, 40, 36, 5, 0},
        {P.cW1,                              S_CW1, 128, 64, 64, 8, 1},
        {P.cW2,                              S_CW2,  64, 64, 64, 8, 1},
        {P.cW3,                              S_CW3,  64,  8,  1, 1, 0},
        {P.fW1 + (size_t)(3 * 132 + 4) * 32, S_F3,  128, 32, 32, 4, 1},
        {P.fW1 + (size_t)(2 * 132 + 4) * 32, S_F2,  128, 32, 32, 4, 1},
        {P.fW1 + (size_t)(1 * 132 + 4) * 32, S_F1,  128, 32, 32, 4, 1},
        {P.fW1 + (size_t)(0 * 132 + 4) * 32, S_F0,  128, 32, 32, 4, 1},
    };
    int idx = blockIdx.x * blockDim.x + threadIdx.x;
    for (int gi = 0; gi < 13; ++gi) {
        int tot = gd[gi].K * gd[gi].NP;
        if (idx < tot) {
            int k = idx / gd[gi].NP, n = idx % gd[gi].NP;
            int kt = k >> 3, nt = n >> 3;
            int lanep = (n & 7) * 4 + (k & 3);
            int khalf = (k >> 2) & 1;
            int pos;
            if (gd[gi].paired) {
                int ntp = gd[gi].NT >> 1;
                int p = nt >> 1, q = nt & 1;
                pos = (((kt * ntp + p) * 32) + lanep) * 4 + q * 2 + khalf;
            } else {
                pos = (((kt * gd[gi].NT + nt) * 32) + lanep) * 2 + khalf;
            }
            float v = (n < gd[gi].NR) ? to_tf32(gd[gi].s[(size_t)k * gd[gi].NR + n]) : 0.f;
            g_wscratch[gd[gi].off + pos] = v;
            return;
        }
        idx -= tot;
    }
}

// ---- contiguous 16B async copy from scratch ----
__device__ __forceinline__ void stage_lin(float* dst, const float* src, int nfloats, int tid) {
    for (int i = tid * 4; i < nfloats; i += THREADS * 4) {
        uint32_t s = (uint32_t)__cvta_generic_to_shared(dst + i);
        asm volatile("cp.async.cg.shared.global [%0], [%1], 16;" :: "r"(s), "l"(src + i));
    }
}
__device__ __forceinline__ void cp_commit() { asm volatile("cp.async.commit_group;"); }
template<int N> __device__ __forceinline__ void cp_wait() {
    asm volatile("cp.async.wait_group %0;" :: "n"(N));
}

// ---- tf32 mma m16n8k8 ----
__device__ __forceinline__ void mma8(float* c, uint32_t a0, uint32_t a1, uint32_t a2, uint32_t a3,
                                     uint32_t b0, uint32_t b1) {
    asm volatile("mma.sync.aligned.m16n8k8.row.col.f32.tf32.tf32.f32 "
                 "{%0,%1,%2,%3}, {%4,%5,%6,%7}, {%8,%9}, {%0,%1,%2,%3};"
                 : "+f"(c[0]), "+f"(c[1]), "+f"(c[2]), "+f"(c[3])
                 : "r"(a0), "r"(a1), "r"(a2), "r"(a3), "r"(b0), "r"(b1));
}

// legacy float2-B gemm (for NT=1 / odd-NT matrices: mW, hW, cW3)
template<int KT, int NTtot, int NTloc>
__device__ __forceinline__ void gemm_frag(const float* __restrict__ A, const float* __restrict__ B,
                                          const float* __restrict__ bias,
                                          float (&acc)[NTloc][4], int lane, int t, int ntBase) {
#pragma unroll
    for (int nt = 0; nt < NTloc; ++nt) {
        float b0 = bias[(ntBase + nt) * 8 + 2 * t], b1 = bias[(ntBase + nt) * 8 + 2 * t + 1];
        acc[nt][0] = b0; acc[nt][1] = b1; acc[nt][2] = b0; acc[nt][3] = b1;
    }
#pragma unroll 4
    for (int kt = 0; kt < KT; ++kt) {
        float4 av = *reinterpret_cast<const float4*>(A + (kt * 32 + lane) * 4);
        uint32_t a0 = __float_as_uint(av.x), a1 = __float_as_uint(av.y);
        uint32_t a2 = __float_as_uint(av.z), a3 = __float_as_uint(av.w);
#pragma unroll
        for (int nt = 0; nt < NTloc; ++nt) {
            float2 bv = *reinterpret_cast<const float2*>(B + ((kt * NTtot + ntBase + nt) * 32 + lane) * 2);
            mma8(acc[nt], a0, a1, a2, a3, __float_as_uint(bv.x), __float_as_uint(bv.y));
        }
    }
}

// paired-B gemm: one LDS.128 feeds two mmas. NTPtot pairs total in layout,
// warp computes NTPloc pairs starting at pair pBase. acc tile i = nt (pBase*2 + i).
template<int KT, int NTPtot, int NTPloc>
__device__ __forceinline__ void gemm_frag_p(const float* __restrict__ A, const float* __restrict__ B,
                                            const float* __restrict__ bias,
                                            float (&acc)[2 * NTPloc][4], int lane, int t, int pBase) {
#pragma unroll
    for (int i = 0; i < 2 * NTPloc; ++i) {
        float b0 = bias[(pBase * 2 + i) * 8 + 2 * t], b1 = bias[(pBase * 2 + i) * 8 + 2 * t + 1];
        acc[i][0] = b0; acc[i][1] = b1; acc[i][2] = b0; acc[i][3] = b1;
    }
#pragma unroll 4
    for (int kt = 0; kt < KT; ++kt) {
        float4 av = *reinterpret_cast<const float4*>(A + (kt * 32 + lane) * 4);
        uint32_t a0 = __float_as_uint(av.x), a1 = __float_as_uint(av.y);
        uint32_t a2 = __float_as_uint(av.z), a3 = __float_as_uint(av.w);
#pragma unroll
        for (int p = 0; p < NTPloc; ++p) {
            float4 bv = *reinterpret_cast<const float4*>(B + ((kt * NTPtot + pBase + p) * 32 + lane) * 4);
            mma8(acc[2 * p],     a0, a1, a2, a3, __float_as_uint(bv.x), __float_as_uint(bv.y));
            mma8(acc[2 * p + 1], a0, a1, a2, a3, __float_as_uint(bv.z), __float_as_uint(bv.w));
        }
    }
}

__device__ __forceinline__ void store_act(float* buf, int mtile, int rl, int col, float v) {
    int kt = col >> 3, kin = col & 7;
    buf[(((mtile << 3) + kt) * 32 + ((rl & 7) << 2) + (kin & 3)) * 4 +
        ((rl >> 3) & 1) + (((kin >> 2) & 1) << 1)] = v;
}

template<int NTloc>
__device__ __forceinline__ void epi_silu(float (&acc)[NTloc][4], float* dst, int mtile,
                                         int g, int t, int ntBase) {
#pragma unroll
    for (int nt = 0; nt < NTloc; ++nt) {
        int c0 = (ntBase + nt) * 8 + 2 * t;
        store_act(dst, mtile, g,     c0,     to_tf32(siluf(acc[nt][0])));
        store_act(dst, mtile, g,     c0 + 1, to_tf32(siluf(acc[nt][1])));
        store_act(dst, mtile, g + 8, c0,     to_tf32(siluf(acc[nt][2])));
        store_act(dst, mtile, g + 8, c0 + 1, to_tf32(siluf(acc[nt][3])));
    }
}

template<int NTloc>
__device__ __forceinline__ void epi_silu_rms(float (&acc)[NTloc][4], float* dst, const float* w,
                                             int mtile, int g, int t, int nh, float* rsum) {
    float s_lo = 0.f, s_hi = 0.f;
#pragma unroll
    for (int nt = 0; nt < NTloc; ++nt) {
        acc[nt][0] = siluf(acc[nt][0]); acc[nt][1] = siluf(acc[nt][1]);
        acc[nt][2] = siluf(acc[nt][2]); acc[nt][3] = siluf(acc[nt][3]);
        s_lo += acc[nt][0] * acc[nt][0] + acc[nt][1] * acc[nt][1];
        s_hi += acc[nt][2] * acc[nt][2] + acc[nt][3] * acc[nt][3];
    }
    s_lo += __shfl_xor_sync(0xffffffffu, s_lo, 1);
    s_lo += __shfl_xor_sync(0xffffffffu, s_lo, 2);
    s_hi += __shfl_xor_sync(0xffffffffu, s_hi, 1);
    s_hi += __shfl_xor_sync(0xffffffffu, s_hi, 2);
    int rlo = mtile * 16 + g, rhi = rlo + 8;
    if (t == 0) { rsum[rlo * 2 + nh] = s_lo; rsum[rhi * 2 + nh] = s_hi; }
    __syncthreads();
    const float EPSF = 1.1920928955078125e-07f;
    float sc_lo = rsqrtf((rsum[rlo * 2] + rsum[rlo * 2 + 1]) * (1.f / 64.f) + EPSF);
    float sc_hi = rsqrtf((rsum[rhi * 2] + rsum[rhi * 2 + 1]) * (1.f / 64.f) + EPSF);
#pragma unroll
    for (int nt = 0; nt < NTloc; ++nt) {
        int c0 = (nh * NTloc + nt) * 8 + 2 * t;
        store_act(dst, mtile, g,     c0,     to_tf32(acc[nt][0] * sc_lo * w[c0]));
        store_act(dst, mtile, g,     c0 + 1, to_tf32(acc[nt][1] * sc_lo * w[c0 + 1]));
        store_act(dst, mtile, g + 8, c0,     to_tf32(acc[nt][2] * sc_hi * w[c0]));
        store_act(dst, mtile, g + 8, c0 + 1, to_tf32(acc[nt][3] * sc_hi * w[c0 + 1]));
    }
}

__global__ void __launch_bounds__(THREADS) fused_agent_tc(Params P) {
    extern __shared__ float sm[];
    float* xs   = sm + XS_OFF;
    float* wbA  = sm + WBA_OFF;
    float* wbB  = sm + WBB_OFF;
    float* actA = sm + ACTA_OFF;
    float* actB = sm + ACTB_OFF;
    float* amv  = sm + AMV_OFF;
    float* lr   = sm + LR_OFF;
    float* cst  = sm + CST_OFF;
    float* rsum = sm + RS_OFF;

    const int tid = threadIdx.x;
    const int warp = tid >> 5;
    const int lane = tid & 31;
    const int g = lane >> 2;
    const int t = lane & 3;
    const int mtile = warp >> 1;
    const int nh = warp & 1;

    // ---- prefetch first two weight groups (pure contiguous 16B copies) ----
    stage_lin(wbA, g_wscratch + S_AW1, 8192, tid); cp_commit();            // g1
    stage_lin(wbB, g_wscratch + S_AW2, 4608, tid); cp_commit();            // g2 (aW2+mW)

    // ---- stage X into A-fragment layout (tf32-rounded, float4 loads) ----
    {
        const float* gx = P.x + (size_t)blockIdx.x * ROWS * OBS;
        for (int i = tid * 4; i < ROWS * OBS; i += THREADS * 4) {
            float4 v4 = *reinterpret_cast<const float4*>(gx + i);
            int row = i >> 7, col = i & 127;
            int mt = row >> 4, kt = col >> 3;
            float vv[4] = {v4.x, v4.y, v4.z, v4.w};
#pragma unroll
            for (int e = 0; e < 4; ++e) {
                int kin = (col + e) & 7;
                xs[((mt * 16 + kt) * 32 + (row & 7) * 4 + (kin & 3)) * 4 +
                   ((row >> 3) & 1) + (((kin >> 2) & 1) << 1)] = to_tf32(vv[e]);
            }
        }
    }
    // ---- stage consts ----
    for (int i = tid; i < 512; i += THREADS)
        cst[C_FCOND + i] = P.fW1[((i >> 7) * 132 + ((i >> 5) & 3)) * 32 + (i & 31)];
    for (int i = tid; i < 2048; i += THREADS) cst[C_FW2 + i] = P.fW2[i];
    for (int i = tid; i < 128; i += THREADS) cst[C_FB1 + i] = P.fb1[i];
    if (tid < 32) cst[C_FB2 + tid] = P.fb2[tid];
    if (tid < 64) {
        cst[C_AB1 + tid] = P.ab1[tid]; cst[C_AB2 + tid] = P.ab2[tid];
        cst[C_TB1 + tid] = P.tb1[tid]; cst[C_TB2 + tid] = P.tb2[tid];
        cst[C_TR1 + tid] = P.t_rms1[tid]; cst[C_TR2 + tid] = P.t_rms2[tid];
        cst[C_CB1 + tid] = P.cb1[tid]; cst[C_CB2 + tid] = P.cb2[tid];
        cst[C_CRMS + tid] = P.c_rms[tid];
    }
    if (tid < 8) cst[C_MB + tid] = P.mb[tid];
    if (tid < 40) cst[C_HBP + tid] = (tid < 36) ? P.hb[tid] : 0.f;
    if (tid < 8) cst[C_VB + tid] = (tid == 0) ? P.cb3[0] : 0.f;

    cp_wait<1>(); __syncthreads();   // g1 (wbA=aW1) ready

    // ===== A1 = silu(X @ aW1 + ab1) =====
    {
        float acc[4][4];
        gemm_frag_p<16, 4, 2>(xs + mtile * 2048, wbA, cst + C_AB1, acc, lane, t, nh * 2);
        epi_silu<4>(acc, actA, mtile, g, t, nh * 4);
    }
    __syncthreads();                 // wbA consumed, actA written
    stage_lin(wbA, g_wscratch + S_TW1, 8192, tid); cp_commit();            // g3
    cp_wait<1>(); __syncthreads();   // g2 (wbB) ready

    // ===== A2 = silu(A1 @ aW2 + ab2) =====
    {
        float acc[4][4];
        gemm_frag_p<8, 4, 2>(actA + mtile * 1024, wbB, cst + C_AB2, acc, lane, t, nh * 2);
        epi_silu<4>(acc, actB, mtile, g, t, nh * 4);
    }
    __syncthreads();                 // actB written
    // ===== AM = A2 @ mW + mb (even warps, legacy layout) =====
    if (nh == 0) {
        float acc[1][4];
        gemm_frag<8, 1, 1>(actB + mtile * 1024, wbB + 4096, cst + C_MB, acc, lane, t, 0);
        int rlo = mtile * 16 + g, rhi = rlo + 8, c0 = 2 * t;
        amv[rlo * 12 + c0] = acc[0][0]; amv[rlo * 12 + c0 + 1] = acc[0][1];
        amv[rhi * 12 + c0] = acc[0][2]; amv[rhi * 12 + c0 + 1] = acc[0][3];
    }
    __syncthreads();                 // wbB consumed
    stage_lin(wbB, g_wscratch + S_TW2, 6656, tid); cp_commit();            // g4 (tW2+hW)
    cp_wait<1>(); __syncthreads();   // g3 (wbA=tW1) ready

    // ===== T1 = rms(silu(X @ tW1 + tb1), t_rms1) =====
    {
        float acc[4][4];
        gemm_frag_p<16, 4, 2>(xs + mtile * 2048, wbA, cst + C_TB1, acc, lane, t, nh * 2);
        epi_silu_rms<4>(acc, actA, cst + C_TR1, mtile, g, t, nh, rsum);
    }
    __syncthreads();                 // wbA consumed
    stage_lin(wbA, g_wscratch + S_CW1, 8192, tid); cp_commit();            // g5
    cp_wait<1>(); __syncthreads();   // g4 (wbB) ready

    // ===== T2 = rms(silu(T1 @ tW2 + tb2), t_rms2) =====
    {
        float acc[4][4];
        gemm_frag_p<8, 4, 2>(actA + mtile * 1024, wbB, cst + C_TB2, acc, lane, t, nh * 2);
        epi_silu_rms<4>(acc, actB, cst + C_TR2, mtile, g, t, nh, rsum);
    }
    __syncthreads();                 // actB written
    // ===== Lraw = T2 @ hW + hb (legacy layout, split 3/2) =====
    if (nh == 0) {
        float acc[3][4];
        gemm_frag<8, 5, 3>(actB + mtile * 1024, wbB + 4096, cst + C_HBP, acc, lane, t, 0);
        int rlo = mtile * 16 + g, rhi = rlo + 8;
#pragma unroll
        for (int nt = 0; nt < 3; ++nt) {
            int c0 = nt * 8 + 2 * t;
            lr[rlo * 40 + c0] = acc[nt][0]; lr[rlo * 40 + c0 + 1] = acc[nt][1];
            lr[rhi * 40 + c0] = acc[nt][2]; lr[rhi * 40 + c0 + 1] = acc[nt][3];
        }
    } else {
        float acc[2][4];
        gemm_frag<8, 5, 2>(actB + mtile * 1024, wbB + 4096, cst + C_HBP, acc, lane, t, 3);
        int rlo = mtile * 16 + g, rhi = rlo + 8;
#pragma unroll
        for (int nt = 0; nt < 2; ++nt) {
            int c0 = (3 + nt) * 8 + 2 * t;
            lr[rlo * 40 + c0] = acc[nt][0]; lr[rlo * 40 + c0 + 1] = acc[nt][1];
            lr[rhi * 40 + c0] = acc[nt][2]; lr[rhi * 40 + c0 + 1] = acc[nt][3];
        }
    }
    __syncthreads();                 // wbB consumed
    stage_lin(wbB, g_wscratch + S_CW2, 4608, tid); cp_commit();            // g6 (cW2+cW3)
    cp_wait<1>(); __syncthreads();   // g5 (wbA=cW1) ready

    // ===== C1 = rms(silu(X @ cW1 + cb1), c_rms) =====
    {
        float acc[4][4];
        gemm_frag_p<16, 4, 2>(xs + mtile * 2048, wbA, cst + C_CB1, acc, lane, t, nh * 2);
        epi_silu_rms<4>(acc, actA, cst + C_CRMS, mtile, g, t, nh, rsum);
    }
    __syncthreads();                 // wbA consumed
    stage_lin(wbA, g_wscratch + S_F3, 8192, tid); cp_commit();             // g7 (fW1 l3,l2)
    cp_wait<1>(); __syncthreads();   // g6 (wbB) ready

    // ===== C2 = silu(C1 @ cW2 + cb2) =====
    {
        float acc[4][4];
        gemm_frag_p<8, 4, 2>(actA + mtile * 1024, wbB, cst + C_CB2, acc, lane, t, nh * 2);
        epi_silu<4>(acc, actB, mtile, g, t, nh * 4);
    }
    __syncthreads();                 // actB written
    // ===== v = C2 @ cW3 + cb3 (even warps, legacy layout) =====
    if (nh == 0) {
        float acc[1][4];
        gemm_frag<8, 1, 1>(actB + mtile * 1024, wbB + 4096, cst + C_VB, acc, lane, t, 0);
        if (t == 0) {
            int rlo = mtile * 16 + g, rhi = rlo + 8;
            amv[rlo * 12 + 8] = acc[0][0];
            amv[rhi * 12 + 8] = acc[0][2];
        }
    }
    __syncthreads();                 // wbB consumed, actA free
    stage_lin(wbB, g_wscratch + S_F1, 4096, tid); cp_commit();             // g8 (fW1 l1)
    cp_wait<1>(); __syncthreads();   // g7 (wbA) ready

    // ===== U3 & U2 concurrent =====
    float* ub = actA;
    {
        const int l = 3 - (warp >> 3);
        const int mloc = warp & 7;
        const float* Bw = wbA + (warp >> 3) * 4096;
        float acc[4][4];
        gemm_frag_p<16, 2, 2>(xs + mloc * 2048, Bw, cst + C_FB1 + l * 32, acc, lane, t, 0);
        int rlo = mloc * 16 + g, rhi = rlo + 8;
#pragma unroll
        for (int nt = 0; nt < 4; ++nt) {
            int c0 = nt * 8 + 2 * t;
            ub[(l * 128 + rlo) * 32 + ((c0 + rlo) & 31)]     = acc[nt][0];
            ub[(l * 128 + rlo) * 32 + ((c0 + 1 + rlo) & 31)] = acc[nt][1];
            ub[(l * 128 + rhi) * 32 + ((c0 + rhi) & 31)]     = acc[nt][2];
            ub[(l * 128 + rhi) * 32 + ((c0 + 1 + rhi) & 31)] = acc[nt][3];
        }
    }
    __syncthreads();                 // wbA consumed
    stage_lin(wbA, g_wscratch + S_F0, 4096, tid); cp_commit();             // g9 (fW1 l0)
    cp_wait<1>(); __syncthreads();   // g8 (wbB) ready

    // ===== U1 =====
    {
        const int l = 1;
        float acc[2][4];
        gemm_frag_p<16, 2, 1>(xs + mtile * 2048, wbB, cst + C_FB1 + l * 32, acc, lane, t, nh);
        int rlo = mtile * 16 + g, rhi = rlo + 8;
#pragma unroll
        for (int nt = 0; nt < 2; ++nt) {
            int c0 = (nh * 2 + nt) * 8 + 2 * t;
            ub[(l * 128 + rlo) * 32 + ((c0 + rlo) & 31)]     = acc[nt][0];
            ub[(l * 128 + rlo) * 32 + ((c0 + 1 + rlo) & 31)] = acc[nt][1];
            ub[(l * 128 + rhi) * 32 + ((c0 + rhi) & 31)]     = acc[nt][2];
            ub[(l * 128 + rhi) * 32 + ((c0 + 1 + rhi) & 31)] = acc[nt][3];
        }
    }
    cp_wait<0>(); __syncthreads();   // g9 (wbA) ready
    // ===== U0 =====
    {
        const int l = 0;
        float acc[2][4];
        gemm_frag_p<16, 2, 1>(xs + mtile * 2048, wbA, cst + C_FB1 + l * 32, acc, lane, t, nh);
        int rlo = mtile * 16 + g, rhi = rlo + 8;
#pragma unroll
        for (int nt = 0; nt < 2; ++nt) {
            int c0 = (nh * 2 + nt) * 8 + 2 * t;
            ub[(l * 128 + rlo) * 32 + ((c0 + rlo) & 31)]     = acc[nt][0];
            ub[(l * 128 + rlo) * 32 + ((c0 + 1 + rlo) & 31)] = acc[nt][1];
            ub[(l * 128 + rhi) * 32 + ((c0 + rhi) & 31)]     = acc[nt][2];
            ub[(l * 128 + rhi) * 32 + ((c0 + 1 + rhi) & 31)] = acc[nt][3];
        }
    }
    __syncthreads();

    // =================== SIMT tail: 4 threads per row ===================
    const int r = (warp << 3) + (lane >> 2);
    const int quarter = lane & 3;
    const size_t grow = (size_t)blockIdx.x * ROWS + r;
    const size_t Bq = (size_t)P.B;

    float4 a0 = *reinterpret_cast<const float4*>(P.action + grow * 8);
    float4 a1 = *reinterpret_cast<const float4*>(P.action + grow * 8 + 4);
    float4 z0 = *reinterpret_cast<const float4*>(P.z_rpo + grow * 8);
    float4 z1 = *reinterpret_cast<const float4*>(P.z_rpo + grow * 8 + 4);

    float x1v[4], x2v[4];
    x1v[0] = a0.x - amv[r * 12 + 0] - z0.x;
    x1v[1] = a0.y - amv[r * 12 + 1] - z0.y;
    x1v[2] = a0.z - amv[r * 12 + 2] - z0.z;
    x1v[3] = a0.w - amv[r * 12 + 3] - z0.w;
    x2v[0] = a1.x - amv[r * 12 + 4] - z1.x;
    x2v[1] = a1.y - amv[r * 12 + 5] - z1.y;
    x2v[2] = a1.z - amv[r * 12 + 6] - z1.z;
    x2v[3] = a1.w - amv[r * 12 + 7] - z1.w;

    const float* fcond = cst + C_FCOND;
    const float* fW2s  = cst + C_FW2;
    const float* fb2s  = cst + C_FB2;

    float fld = 0.f;
#pragma unroll
    for (int it = 0; it < NL; ++it) {
        const int i = NL - 1 - it;
        float* condp = (i % 2 == 0) ? x1v : x2v;
        float* yp    = (i % 2 == 0) ? x2v : x1v;
        float u[8];
#pragma unroll
        for (int jj = 0; jj < 8; ++jj) {
            int j = quarter * 8 + jj;
            u[jj] = ub[(i * 128 + r) * 32 + ((j + r) & 31)];
        }
#pragma unroll
        for (int c = 0; c < 4; ++c) {
            float cv = condp[c];
#pragma unroll
            for (int jj = 0; jj < 8; ++jj)
                u[jj] = fmaf(cv, fcond[(i * 4 + c) * 32 + quarter * 8 + jj], u[jj]);
        }
#pragma unroll
        for (int jj = 0; jj < 8; ++jj) u[jj] = siluf(u[jj]);
        float stp[8];
#pragma unroll
        for (int m = 0; m < 8; ++m) stp[m] = (quarter == 0) ? fb2s[i * 8 + m] : 0.f;
#pragma unroll
        for (int jj = 0; jj < 8; ++jj) {
            float uv = u[jj];
            const float* wrow = fW2s + (i * 32 + quarter * 8 + jj) * 8;
#pragma unroll
            for (int m = 0; m < 8; ++m) stp[m] = fmaf(uv, wrow[m], stp[m]);
        }
#pragma unroll
        for (int m = 0; m < 8; ++m) {
            stp[m] += __shfl_xor_sync(0xffffffffu, stp[m], 1);
            stp[m] += __shfl_xor_sync(0xffffffffu, stp[m], 2);
        }
#pragma unroll
        for (int m = 0; m < 4; ++m) {
            float s = 2.f * tanhf(stp[m]);
            fld += s;
            yp[m] = (yp[m] - stp[4 + m]) * __expf(-s);
        }
    }

    float Lm[36];
#pragma unroll
    for (int i = 0; i < 36; ++i) Lm[i] = lr[r * 40 + i];
    float log_det = 0.f;
#pragma unroll
    for (int i = 0; i < 8; ++i) {
        int d = i * (i + 3) / 2;
        float rv = Lm[d];
        float sp = fmaxf(rv, 0.f) + log1pf(__expf(-fabsf(rv)));
        Lm[d] = sp;
        log_det += __logf(sp);
    }
    float corr[8] = {x1v[0], x1v[1], x1v[2], x1v[3], x2v[0], x2v[1], x2v[2], x2v[3]};
    float zv[8];
#pragma unroll
    for (int i = 0; i < 8; ++i) {
        float acc = corr[i];
#pragma unroll
        for (int j = 0; j < 8; ++j)
            if (j < i) acc -= Lm[i * (i + 1) / 2 + j] * zv[j];
        zv[i] = acc / Lm[i * (i + 1) / 2 + i];
    }
    float mahal = 0.f;
#pragma unroll
    for (int i = 0; i < 8; ++i) mahal += zv[i] * zv[i];
    const float LOG2PIf = 1.8378770664093453f;
    float lp  = -0.5f * (8.f * LOG2PIf + mahal) - log_det - fld;
    float ent = 0.5f * (8.f * (1.f + LOG2PIf)) + log_det + fld;

    if (quarter == 0) {
        *reinterpret_cast<float4*>(P.out + grow * 8)     = a0;
        *reinterpret_cast<float4*>(P.out + grow * 8 + 4) = a1;
        P.out[Bq * 8 + grow]  = lp;
        P.out[Bq * 9 + grow]  = ent;
        P.out[Bq * 10 + grow] = amv[r * 12 + 8];
    }
}

extern "C" void kernel_launch(void* const* d_in, const int* in_sizes, int n_in,
                              void* d_out, int out_size) {
    (void)n_in; (void)out_size;
    Params P;
    P.x      = (const float*)d_in[0];
    P.action = (const float*)d_in[1];
    P.z_rpo  = (const float*)d_in[2];
    P.cW1    = (const float*)d_in[3];
    P.cb1    = (const float*)d_in[4];
    P.c_rms  = (const float*)d_in[5];
    P.cW2    = (const float*)d_in[6];
    P.cb2    = (const float*)d_in[7];
    P.cW3    = (const float*)d_in[8];
    P.cb3    = (const float*)d_in[9];
    P.aW1    = (const float*)d_in[10];
    P.ab1    = (const float*)d_in[11];
    P.aW2    = (const float*)d_in[12];
    P.ab2    = (const float*)d_in[13];
    P.mW     = (const float*)d_in[14];
    P.mb     = (const float*)d_in[15];
    P.tW1    = (const float*)d_in[16];
    P.tb1    = (const float*)d_in[17];
    P.t_rms1 = (const float*)d_in[18];
    P.tW2    = (const float*)d_in[19];
    P.tb2    = (const float*)d_in[20];
    P.t_rms2 = (const float*)d_in[21];
    P.hW     = (const float*)d_in[22];
    P.hb     = (const float*)d_in[23];
    P.fW1    = (const float*)d_in[24];
    P.fb1    = (const float*)d_in[25];
    P.fW2    = (const float*)d_in[26];
    P.fb2    = (const float*)d_in[27];
    P.out    = (float*)d_out;
    P.B      = in_sizes[0] / OBS;

    prep_weights<<<(SCRATCH_F + 255) / 256, 256>>>(P);
    cudaFuncSetAttribute(fused_agent_tc,
                         cudaFuncAttributeMaxDynamicSharedMemorySize, SMEM_BYTES);
    fused_agent_tc<<<P.B / ROWS, THREADS, SMEM_BYTES>>>(P);
}

// round 16
// speedup vs baseline: 2.9840x; 1.0134x over previous
#include <cuda_runtime.h>
#include <cstdint>

#define THREADS 512
#define ROWS 128
#define OBS 128
#define H 64
#define AD 8
#define FH 32
#define NL 4

// ---------------- smem layout (floats) ----------------
#define XS_OFF    0
#define XS_F      16384
#define WBA_OFF   (XS_OFF + XS_F)
#define WBA_F     8192
#define WBB_OFF   (WBA_OFF + WBA_F)
#define WBB_F     6656
#define ACTA_OFF  (WBB_OFF + WBB_F)
#define ACTA_F    8192
#define ACTB_OFF  (ACTA_OFF + ACTA_F)
#define ACTB_F    8192
#define AMV_OFF   (ACTB_OFF + ACTB_F)
#define AMV_F     (128*12)
#define LR_OFF    (AMV_OFF + AMV_F)
#define LR_F      (128*40)
#define CST_OFF   (LR_OFF + LR_F)
#define C_FCOND 0
#define C_FW2   512
#define C_FB1   2560
#define C_FB2   2688
#define C_AB1   2720
#define C_AB2   2784
#define C_MB    2848
#define C_TB1   2856
#define C_TB2   2920
#define C_TR1   2984
#define C_TR2   3048
#define C_HBP   3112
#define C_CB1   3152
#define C_CB2   3216
#define C_CRMS  3280
#define C_VB    3344
#define CST_F   3352
#define RS_OFF  (CST_OFF + CST_F)
#define RS_F    256
#define SMEM_F  (RS_OFF + RS_F)
#define SMEM_BYTES (SMEM_F * 4)

// ---------------- weight scratch (pre-rounded, pre-layouted) ----------------
#define S_AW1 0
#define S_AW2 8192
#define S_MW  12288
#define S_TW1 12800
#define S_TW2 20992
#define S_HW  25088
#define S_CW1 27648
#define S_CW2 35840
#define S_CW3 39936
#define S_F3  40448
#define S_F2  44544
#define S_F1  48640
#define S_F0  52736
#define SCRATCH_F 56832

__device__ __align__(16) float g_wscratch[SCRATCH_F];

struct Params {
    const float *x, *action, *z_rpo;
    const float *cW1, *cb1, *c_rms, *cW2, *cb2, *cW3, *cb3;
    const float *aW1, *ab1, *aW2, *ab2, *mW, *mb;
    const float *tW1, *tb1, *t_rms1, *tW2, *tb2, *t_rms2, *hW, *hb;
    const float *fW1, *fb1, *fW2, *fb2;
    float *out;
    int B;
};

__device__ __forceinline__ float siluf(float v) {
    return __fdividef(v, 1.f + __expf(-v));
}

__device__ __forceinline__ float to_tf32(float f) {
    uint32_t o;
    asm("cvt.rna.tf32.f32 %0, %1;" : "=r"(o) : "f"(f));
    return __uint_as_float(o);
}

// ================= prep kernel: round + fragment-layout all weights once =================
// paired=1: two adjacent n-tiles interleaved so one float4 per lane feeds two mmas.
__global__ void prep_weights(Params P) {
    struct GD { const float* s; int off, K, NP, NR, NT, paired; };
    GD gd[13] = {
        {P.aW1,                              S_AW1, 128, 64, 64, 8, 1},
        {P.aW2,                              S_AW2,  64, 64, 64, 8, 1},
        {P.mW,                               S_MW,   64,  8,  8, 1, 0},
        {P.tW1,                              S_TW1, 128, 64, 64, 8, 1},
        {P.tW2,                              S_TW2,  64, 64, 64, 8, 1},
        {P.hW,                               S_HW,   64, 40, 36, 5, 0},
        {P.cW1,                              S_CW1, 128, 64, 64, 8, 1},
        {P.cW2,                              S_CW2,  64, 64, 64, 8, 1},
        {P.cW3,                              S_CW3,  64,  8,  1, 1, 0},
        {P.fW1 + (size_t)(3 * 132 + 4) * 32, S_F3,  128, 32, 32, 4, 1},
        {P.fW1 + (size_t)(2 * 132 + 4) * 32, S_F2,  128, 32, 32, 4, 1},
        {P.fW1 + (size_t)(1 * 132 + 4) * 32, S_F1,  128, 32, 32, 4, 1},
        {P.fW1 + (size_t)(0 * 132 + 4) * 32, S_F0,  128, 32, 32, 4, 1},
    };
    int idx = blockIdx.x * blockDim.x + threadIdx.x;
    for (int gi = 0; gi < 13; ++gi) {
        int tot = gd[gi].K * gd[gi].NP;
        if (idx < tot) {
            int k = idx / gd[gi].NP, n = idx % gd[gi].NP;
            int kt = k >> 3, nt = n >> 3;
            int lanep = (n & 7) * 4 + (k & 3);
            int khalf = (k >> 2) & 1;
            int pos;
            if (gd[gi].paired) {
                int ntp = gd[gi].NT >> 1;
                int p = nt >> 1, q = nt & 1;
                pos = (((kt * ntp + p) * 32) + lanep) * 4 + q * 2 + khalf;
            } else {
                pos = (((kt * gd[gi].NT + nt) * 32) + lanep) * 2 + khalf;
            }
            float v = (n < gd[gi].NR) ? to_tf32(gd[gi].s[(size_t)k * gd[gi].NR + n]) : 0.f;
            g_wscratch[gd[gi].off + pos] = v;
            return;
        }
        idx -= tot;
    }
}

// ---- contiguous 16B async copy from scratch ----
__device__ __forceinline__ void stage_lin(float* dst, const float* src, int nfloats, int tid) {
    for (int i = tid * 4; i < nfloats; i += THREADS * 4) {
        uint32_t s = (uint32_t)__cvta_generic_to_shared(dst + i);
        asm volatile("cp.async.cg.shared.global [%0], [%1], 16;" :: "r"(s), "l"(src + i));
    }
}
__device__ __forceinline__ void cp_commit() { asm volatile("cp.async.commit_group;"); }
template<int N> __device__ __forceinline__ void cp_wait() {
    asm volatile("cp.async.wait_group %0;" :: "n"(N));
}

// ---- tf32 mma m16n8k8 ----
__device__ __forceinline__ void mma8(float* c, uint32_t a0, uint32_t a1, uint32_t a2, uint32_t a3,
                                     uint32_t b0, uint32_t b1) {
    asm volatile("mma.sync.aligned.m16n8k8.row.col.f32.tf32.tf32.f32 "
                 "{%0,%1,%2,%3}, {%4,%5,%6,%7}, {%8,%9}, {%0,%1,%2,%3};"
                 : "+f"(c[0]), "+f"(c[1]), "+f"(c[2]), "+f"(c[3])
                 : "r"(a0), "r"(a1), "r"(a2), "r"(a3), "r"(b0), "r"(b1));
}

// legacy float2-B gemm (for NT=1 / odd-NT matrices: mW, hW, cW3)
template<int KT, int NTtot, int NTloc>
__device__ __forceinline__ void gemm_frag(const float* __restrict__ A, const float* __restrict__ B,
                                          const float* __restrict__ bias,
                                          float (&acc)[NTloc][4], int lane, int t, int ntBase) {
#pragma unroll
    for (int nt = 0; nt < NTloc; ++nt) {
        float b0 = bias[(ntBase + nt) * 8 + 2 * t], b1 = bias[(ntBase + nt) * 8 + 2 * t + 1];
        acc[nt][0] = b0; acc[nt][1] = b1; acc[nt][2] = b0; acc[nt][3] = b1;
    }
#pragma unroll 4
    for (int kt = 0; kt < KT; ++kt) {
        float4 av = *reinterpret_cast<const float4*>(A + (kt * 32 + lane) * 4);
        uint32_t a0 = __float_as_uint(av.x), a1 = __float_as_uint(av.y);
        uint32_t a2 = __float_as_uint(av.z), a3 = __float_as_uint(av.w);
#pragma unroll
        for (int nt = 0; nt < NTloc; ++nt) {
            float2 bv = *reinterpret_cast<const float2*>(B + ((kt * NTtot + ntBase + nt) * 32 + lane) * 2);
            mma8(acc[nt], a0, a1, a2, a3, __float_as_uint(bv.x), __float_as_uint(bv.y));
        }
    }
}

// paired-B gemm: one LDS.128 feeds two mmas.
template<int KT, int NTPtot, int NTPloc>
__device__ __forceinline__ void gemm_frag_p(const float* __restrict__ A, const float* __restrict__ B,
                                            const float* __restrict__ bias,
                                            float (&acc)[2 * NTPloc][4], int lane, int t, int pBase) {
#pragma unroll
    for (int i = 0; i < 2 * NTPloc; ++i) {
        float b0 = bias[(pBase * 2 + i) * 8 + 2 * t], b1 = bias[(pBase * 2 + i) * 8 + 2 * t + 1];
        acc[i][0] = b0; acc[i][1] = b1; acc[i][2] = b0; acc[i][3] = b1;
    }
#pragma unroll 4
    for (int kt = 0; kt < KT; ++kt) {
        float4 av = *reinterpret_cast<const float4*>(A + (kt * 32 + lane) * 4);
        uint32_t a0 = __float_as_uint(av.x), a1 = __float_as_uint(av.y);
        uint32_t a2 = __float_as_uint(av.z), a3 = __float_as_uint(av.w);
#pragma unroll
        for (int p = 0; p < NTPloc; ++p) {
            float4 bv = *reinterpret_cast<const float4*>(B + ((kt * NTPtot + pBase + p) * 32 + lane) * 4);
            mma8(acc[2 * p],     a0, a1, a2, a3, __float_as_uint(bv.x), __float_as_uint(bv.y));
            mma8(acc[2 * p + 1], a0, a1, a2, a3, __float_as_uint(bv.z), __float_as_uint(bv.w));
        }
    }
}

__device__ __forceinline__ void store_act(float* buf, int mtile, int rl, int col, float v) {
    int kt = col >> 3, kin = col & 7;
    buf[(((mtile << 3) + kt) * 32 + ((rl & 7) << 2) + (kin & 3)) * 4 +
        ((rl >> 3) & 1) + (((kin >> 2) & 1) << 1)] = v;
}

template<int NTloc>
__device__ __forceinline__ void epi_silu(float (&acc)[NTloc][4], float* dst, int mtile,
                                         int g, int t, int ntBase) {
#pragma unroll
    for (int nt = 0; nt < NTloc; ++nt) {
        int c0 = (ntBase + nt) * 8 + 2 * t;
        store_act(dst, mtile, g,     c0,     to_tf32(siluf(acc[nt][0])));
        store_act(dst, mtile, g,     c0 + 1, to_tf32(siluf(acc[nt][1])));
        store_act(dst, mtile, g + 8, c0,     to_tf32(siluf(acc[nt][2])));
        store_act(dst, mtile, g + 8, c0 + 1, to_tf32(siluf(acc[nt][3])));
    }
}

template<int NTloc>
__device__ __forceinline__ void epi_silu_rms(float (&acc)[NTloc][4], float* dst, const float* w,
                                             int mtile, int g, int t, int nh, float* rsum) {
    float s_lo = 0.f, s_hi = 0.f;
#pragma unroll
    for (int nt = 0; nt < NTloc; ++nt) {
        acc[nt][0] = siluf(acc[nt][0]); acc[nt][1] = siluf(acc[nt][1]);
        acc[nt][2] = siluf(acc[nt][2]); acc[nt][3] = siluf(acc[nt][3]);
        s_lo += acc[nt][0] * acc[nt][0] + acc[nt][1] * acc[nt][1];
        s_hi += acc[nt][2] * acc[nt][2] + acc[nt][3] * acc[nt][3];
    }
    s_lo += __shfl_xor_sync(0xffffffffu, s_lo, 1);
    s_lo += __shfl_xor_sync(0xffffffffu, s_lo, 2);
    s_hi += __shfl_xor_sync(0xffffffffu, s_hi, 1);
    s_hi += __shfl_xor_sync(0xffffffffu, s_hi, 2);
    int rlo = mtile * 16 + g, rhi = rlo + 8;
    if (t == 0) { rsum[rlo * 2 + nh] = s_lo; rsum[rhi * 2 + nh] = s_hi; }
    __syncthreads();
    const float EPSF = 1.1920928955078125e-07f;
    float sc_lo = rsqrtf((rsum[rlo * 2] + rsum[rlo * 2 + 1]) * (1.f / 64.f) + EPSF);
    float sc_hi = rsqrtf((rsum[rhi * 2] + rsum[rhi * 2 + 1]) * (1.f / 64.f) + EPSF);
#pragma unroll
    for (int nt = 0; nt < NTloc; ++nt) {
        int c0 = (nh * NTloc + nt) * 8 + 2 * t;
        store_act(dst, mtile, g,     c0,     to_tf32(acc[nt][0] * sc_lo * w[c0]));
        store_act(dst, mtile, g,     c0 + 1, to_tf32(acc[nt][1] * sc_lo * w[c0 + 1]));
        store_act(dst, mtile, g + 8, c0,     to_tf32(acc[nt][2] * sc_hi * w[c0]));
        store_act(dst, mtile, g + 8, c0 + 1, to_tf32(acc[nt][3] * sc_hi * w[c0 + 1]));
    }
}

__global__ void __launch_bounds__(THREADS) fused_agent_tc(Params P) {
    extern __shared__ float sm[];
    float* xs   = sm + XS_OFF;
    float* wbA  = sm + WBA_OFF;
    float* wbB  = sm + WBB_OFF;
    float* actA = sm + ACTA_OFF;
    float* actB = sm + ACTB_OFF;
    float* amv  = sm + AMV_OFF;
    float* lr   = sm + LR_OFF;
    float* cst  = sm + CST_OFF;
    float* rsum = sm + RS_OFF;

    const int tid = threadIdx.x;
    const int warp = tid >> 5;
    const int lane = tid & 31;
    const int g = lane >> 2;
    const int t = lane & 3;
    const int mtile = warp >> 1;
    const int nh = warp & 1;

    // ---- prefetch first two weight groups (pure contiguous 16B copies) ----
    stage_lin(wbA, g_wscratch + S_AW1, 8192, tid); cp_commit();            // g1
    stage_lin(wbB, g_wscratch + S_AW2, 4608, tid); cp_commit();            // g2 (aW2+mW)

    // ---- stage X, phase 1: coalesced rows into bounce buffer (aliases act region,
    //      132-pad => conflict-free STS.128) ----
    float* xstage = actA;   // 128*132 = 16896 floats, fits actA+actB+amv span
    {
        const float* gx = P.x + (size_t)blockIdx.x * ROWS * OBS;
        for (int i = tid * 4; i < ROWS * OBS; i += THREADS * 4) {
            float4 v4 = *reinterpret_cast<const float4*>(gx + i);
            int row = i >> 7, col = i & 127;
            *reinterpret_cast<float4*>(xstage + row * 132 + col) = v4;
        }
    }
    // ---- stage consts ----
    for (int i = tid; i < 512; i += THREADS)
        cst[C_FCOND + i] = P.fW1[((i >> 7) * 132 + ((i >> 5) & 3)) * 32 + (i & 31)];
    for (int i = tid; i < 2048; i += THREADS) cst[C_FW2 + i] = P.fW2[i];
    for (int i = tid; i < 128; i += THREADS) cst[C_FB1 + i] = P.fb1[i];
    if (tid < 32) cst[C_FB2 + tid] = P.fb2[tid];
    if (tid < 64) {
        cst[C_AB1 + tid] = P.ab1[tid]; cst[C_AB2 + tid] = P.ab2[tid];
        cst[C_TB1 + tid] = P.tb1[tid]; cst[C_TB2 + tid] = P.tb2[tid];
        cst[C_TR1 + tid] = P.t_rms1[tid]; cst[C_TR2 + tid] = P.t_rms2[tid];
        cst[C_CB1 + tid] = P.cb1[tid]; cst[C_CB2 + tid] = P.cb2[tid];
        cst[C_CRMS + tid] = P.c_rms[tid];
    }
    if (tid < 8) cst[C_MB + tid] = P.mb[tid];
    if (tid < 40) cst[C_HBP + tid] = (tid < 36) ? P.hb[tid] : 0.f;
    if (tid < 8) cst[C_VB + tid] = (tid == 0) ? P.cb3[0] : 0.f;

    __syncthreads();   // xstage visible

    // ---- stage X, phase 2: conflict-free gather (LDS.32 x4, distinct banks)
    //      + tf32 round + conflict-free consecutive STS.128 into A-frag layout ----
    {
#pragma unroll
        for (int s = 0; s < 8; ++s) {
            int of4 = tid + s * THREADS;       // float4 index 0..4095
            int ktg = of4 >> 5;                // mt*16+kt
            int lp  = of4 & 31;
            int rl  = lp >> 2, kl = lp & 3;
            int rowb = (ktg >> 4) * 16 + rl;   // lower-8 row
            int colb = (ktg & 15) * 8 + kl;    // kin<4 col
            const float* bp = xstage + rowb * 132 + colb;
            float4 o;
            o.x = to_tf32(bp[0]);
            o.y = to_tf32(bp[8 * 132]);
            o.z = to_tf32(bp[4]);
            o.w = to_tf32(bp[8 * 132 + 4]);
            *reinterpret_cast<float4*>(xs + of4 * 4) = o;
        }
    }

    cp_wait<1>(); __syncthreads();   // g1 (wbA=aW1) ready; xs visible; xstage free

    // ===== A1 = silu(X @ aW1 + ab1) =====
    {
        float acc[4][4];
        gemm_frag_p<16, 4, 2>(xs + mtile * 2048, wbA, cst + C_AB1, acc, lane, t, nh * 2);
        epi_silu<4>(acc, actA, mtile, g, t, nh * 4);
    }
    __syncthreads();                 // wbA consumed, actA written
    stage_lin(wbA, g_wscratch + S_TW1, 8192, tid); cp_commit();            // g3
    cp_wait<1>(); __syncthreads();   // g2 (wbB) ready

    // ===== A2 = silu(A1 @ aW2 + ab2) =====
    {
        float acc[4][4];
        gemm_frag_p<8, 4, 2>(actA + mtile * 1024, wbB, cst + C_AB2, acc, lane, t, nh * 2);
        epi_silu<4>(acc, actB, mtile, g, t, nh * 4);
    }
    __syncthreads();                 // actB written
    // ===== AM = A2 @ mW + mb (even warps, legacy layout) =====
    if (nh == 0) {
        float acc[1][4];
        gemm_frag<8, 1, 1>(actB + mtile * 1024, wbB + 4096, cst + C_MB, acc, lane, t, 0);
        int rlo = mtile * 16 + g, rhi = rlo + 8, c0 = 2 * t;
        amv[rlo * 12 + c0] = acc[0][0]; amv[rlo * 12 + c0 + 1] = acc[0][1];
        amv[rhi * 12 + c0] = acc[0][2]; amv[rhi * 12 + c0 + 1] = acc[0][3];
    }
    __syncthreads();                 // wbB consumed
    stage_lin(wbB, g_wscratch + S_TW2, 6656, tid); cp_commit();            // g4 (tW2+hW)
    cp_wait<1>(); __syncthreads();   // g3 (wbA=tW1) ready

    // ===== T1 = rms(silu(X @ tW1 + tb1), t_rms1) =====
    {
        float acc[4][4];
        gemm_frag_p<16, 4, 2>(xs + mtile * 2048, wbA, cst + C_TB1, acc, lane, t, nh * 2);
        epi_silu_rms<4>(acc, actA, cst + C_TR1, mtile, g, t, nh, rsum);
    }
    __syncthreads();                 // wbA consumed
    stage_lin(wbA, g_wscratch + S_CW1, 8192, tid); cp_commit();            // g5
    cp_wait<1>(); __syncthreads();   // g4 (wbB) ready

    // ===== T2 = rms(silu(T1 @ tW2 + tb2), t_rms2) =====
    {
        float acc[4][4];
        gemm_frag_p<8, 4, 2>(actA + mtile * 1024, wbB, cst + C_TB2, acc, lane, t, nh * 2);
        epi_silu_rms<4>(acc, actB, cst + C_TR2, mtile, g, t, nh, rsum);
    }
    __syncthreads();                 // actB written
    // ===== Lraw = T2 @ hW + hb (legacy layout, split 3/2) =====
    if (nh == 0) {
        float acc[3][4];
        gemm_frag<8, 5, 3>(actB + mtile * 1024, wbB + 4096, cst + C_HBP, acc, lane, t, 0);
        int rlo = mtile * 16 + g, rhi = rlo + 8;
#pragma unroll
        for (int nt = 0; nt < 3; ++nt) {
            int c0 = nt * 8 + 2 * t;
            lr[rlo * 40 + c0] = acc[nt][0]; lr[rlo * 40 + c0 + 1] = acc[nt][1];
            lr[rhi * 40 + c0] = acc[nt][2]; lr[rhi * 40 + c0 + 1] = acc[nt][3];
        }
    } else {
        float acc[2][4];
        gemm_frag<8, 5, 2>(actB + mtile * 1024, wbB + 4096, cst + C_HBP, acc, lane, t, 3);
        int rlo = mtile * 16 + g, rhi = rlo + 8;
#pragma unroll
        for (int nt = 0; nt < 2; ++nt) {
            int c0 = (3 + nt) * 8 + 2 * t;
            lr[rlo * 40 + c0] = acc[nt][0]; lr[rlo * 40 + c0 + 1] = acc[nt][1];
            lr[rhi * 40 + c0] = acc[nt][2]; lr[rhi * 40 + c0 + 1] = acc[nt][3];
        }
    }
    __syncthreads();                 // wbB consumed
    stage_lin(wbB, g_wscratch + S_CW2, 4608, tid); cp_commit();            // g6 (cW2+cW3)
    cp_wait<1>(); __syncthreads();   // g5 (wbA=cW1) ready

    // ===== C1 = rms(silu(X @ cW1 + cb1), c_rms) =====
    {
        float acc[4][4];
        gemm_frag_p<16, 4, 2>(xs + mtile * 2048, wbA, cst + C_CB1, acc, lane, t, nh * 2);
        epi_silu_rms<4>(acc, actA, cst + C_CRMS, mtile, g, t, nh, rsum);
    }
    __syncthreads();                 // wbA consumed
    stage_lin(wbA, g_wscratch + S_F3, 8192, tid); cp_commit();             // g7 (fW1 l3,l2)
    cp_wait<1>(); __syncthreads();   // g6 (wbB) ready

    // ===== C2 = silu(C1 @ cW2 + cb2) =====
    {
        float acc[4][4];
        gemm_frag_p<8, 4, 2>(actA + mtile * 1024, wbB, cst + C_CB2, acc, lane, t, nh * 2);
        epi_silu<4>(acc, actB, mtile, g, t, nh * 4);
    }
    __syncthreads();                 // actB written
    // ===== v = C2 @ cW3 + cb3 (even warps, legacy layout) =====
    if (nh == 0) {
        float acc[1][4];
        gemm_frag<8, 1, 1>(actB + mtile * 1024, wbB + 4096, cst + C_VB, acc, lane, t, 0);
        if (t == 0) {
            int rlo = mtile * 16 + g, rhi = rlo + 8;
            amv[rlo * 12 + 8] = acc[0][0];
            amv[rhi * 12 + 8] = acc[0][2];
        }
    }
    __syncthreads();                 // wbB consumed, actA free
    stage_lin(wbB, g_wscratch + S_F1, 4096, tid); cp_commit();             // g8 (fW1 l1)
    cp_wait<1>(); __syncthreads();   // g7 (wbA) ready

    // ===== U3 & U2 concurrent =====
    float* ub = actA;
    {
        const int l = 3 - (warp >> 3);
        const int mloc = warp & 7;
        const float* Bw = wbA + (warp >> 3) * 4096;
        float acc[4][4];
        gemm_frag_p<16, 2, 2>(xs + mloc * 2048, Bw, cst + C_FB1 + l * 32, acc, lane, t, 0);
        int rlo = mloc * 16 + g, rhi = rlo + 8;
#pragma unroll
        for (int nt = 0; nt < 4; ++nt) {
            int c0 = nt * 8 + 2 * t;
            ub[(l * 128 + rlo) * 32 + ((c0 + rlo) & 31)]     = acc[nt][0];
            ub[(l * 128 + rlo) * 32 + ((c0 + 1 + rlo) & 31)] = acc[nt][1];
            ub[(l * 128 + rhi) * 32 + ((c0 + rhi) & 31)]     = acc[nt][2];
            ub[(l * 128 + rhi) * 32 + ((c0 + 1 + rhi) & 31)] = acc[nt][3];
        }
    }
    __syncthreads();                 // wbA consumed
    stage_lin(wbA, g_wscratch + S_F0, 4096, tid); cp_commit();             // g9 (fW1 l0)
    cp_wait<1>(); __syncthreads();   // g8 (wbB) ready

    // ===== U1 =====
    {
        const int l = 1;
        float acc[2][4];
        gemm_frag_p<16, 2, 1>(xs + mtile * 2048, wbB, cst + C_FB1 + l * 32, acc, lane, t, nh);
        int rlo = mtile * 16 + g, rhi = rlo + 8;
#pragma unroll
        for (int nt = 0; nt < 2; ++nt) {
            int c0 = (nh * 2 + nt) * 8 + 2 * t;
            ub[(l * 128 + rlo) * 32 + ((c0 + rlo) & 31)]     = acc[nt][0];
            ub[(l * 128 + rlo) * 32 + ((c0 + 1 + rlo) & 31)] = acc[nt][1];
            ub[(l * 128 + rhi) * 32 + ((c0 + rhi) & 31)]     = acc[nt][2];
            ub[(l * 128 + rhi) * 32 + ((c0 + 1 + rhi) & 31)] = acc[nt][3];
        }
    }
    cp_wait<0>(); __syncthreads();   // g9 (wbA) ready
    // ===== U0 =====
    {
        const int l = 0;
        float acc[2][4];
        gemm_frag_p<16, 2, 1>(xs + mtile * 2048, wbA, cst + C_FB1 + l * 32, acc, lane, t, nh);
        int rlo = mtile * 16 + g, rhi = rlo + 8;
#pragma unroll
        for (int nt = 0; nt < 2; ++nt) {
            int c0 = (nh * 2 + nt) * 8 + 2 * t;
            ub[(l * 128 + rlo) * 32 + ((c0 + rlo) & 31)]     = acc[nt][0];
            ub[(l * 128 + rlo) * 32 + ((c0 + 1 + rlo) & 31)] = acc[nt][1];
            ub[(l * 128 + rhi) * 32 + ((c0 + rhi) & 31)]     = acc[nt][2];
            ub[(l * 128 + rhi) * 32 + ((c0 + 1 + rhi) & 31)] = acc[nt][3];
        }
    }
    __syncthreads();

    // =================== SIMT tail: 4 threads per row ===================
    const int r = (warp << 3) + (lane >> 2);
    const int quarter = lane & 3;
    const size_t grow = (size_t)blockIdx.x * ROWS + r;
    const size_t Bq = (size_t)P.B;

    float4 a0 = *reinterpret_cast<const float4*>(P.action + grow * 8);
    float4 a1 = *reinterpret_cast<const float4*>(P.action + grow * 8 + 4);
    float4 z0 = *reinterpret_cast<const float4*>(P.z_rpo + grow * 8);
    float4 z1 = *reinterpret_cast<const float4*>(P.z_rpo + grow * 8 + 4);

    float x1v[4], x2v[4];
    x1v[0] = a0.x - amv[r * 12 + 0] - z0.x;
    x1v[1] = a0.y - amv[r * 12 + 1] - z0.y;
    x1v[2] = a0.z - amv[r * 12 + 2] - z0.z;
    x1v[3] = a0.w - amv[r * 12 + 3] - z0.w;
    x2v[0] = a1.x - amv[r * 12 + 4] - z1.x;
    x2v[1] = a1.y - amv[r * 12 + 5] - z1.y;
    x2v[2] = a1.z - amv[r * 12 + 6] - z1.z;
    x2v[3] = a1.w - amv[r * 12 + 7] - z1.w;

    const float* fcond = cst + C_FCOND;
    const float* fW2s  = cst + C_FW2;
    const float* fb2s  = cst + C_FB2;

    float fld = 0.f;
#pragma unroll
    for (int it = 0; it < NL; ++it) {
        const int i = NL - 1 - it;
        float* condp = (i % 2 == 0) ? x1v : x2v;
        float* yp    = (i % 2 == 0) ? x2v : x1v;
        float u[8];
#pragma unroll
        for (int jj = 0; jj < 8; ++jj) {
            int j = quarter * 8 + jj;
            u[jj] = ub[(i * 128 + r) * 32 + ((j + r) & 31)];
        }
#pragma unroll
        for (int c = 0; c < 4; ++c) {
            float cv = condp[c];
#pragma unroll
            for (int jj = 0; jj < 8; ++jj)
                u[jj] = fmaf(cv, fcond[(i * 4 + c) * 32 + quarter * 8 + jj], u[jj]);
        }
#pragma unroll
        for (int jj = 0; jj < 8; ++jj) u[jj] = siluf(u[jj]);
        float stp[8];
#pragma unroll
        for (int m = 0; m < 8; ++m) stp[m] = (quarter == 0) ? fb2s[i * 8 + m] : 0.f;
#pragma unroll
        for (int jj = 0; jj < 8; ++jj) {
            float uv = u[jj];
            const float* wrow = fW2s + (i * 32 + quarter * 8 + jj) * 8;
#pragma unroll
            for (int m = 0; m < 8; ++m) stp[m] = fmaf(uv, wrow[m], stp[m]);
        }
#pragma unroll
        for (int m = 0; m < 8; ++m) {
            stp[m] += __shfl_xor_sync(0xffffffffu, stp[m], 1);
            stp[m] += __shfl_xor_sync(0xffffffffu, stp[m], 2);
        }
#pragma unroll
        for (int m = 0; m < 4; ++m) {
            float s = 2.f * tanhf(stp[m]);
            fld += s;
            yp[m] = (yp[m] - stp[4 + m]) * __expf(-s);
        }
    }

    float Lm[36];
#pragma unroll
    for (int i = 0; i < 36; ++i) Lm[i] = lr[r * 40 + i];
    float log_det = 0.f;
#pragma unroll
    for (int i = 0; i < 8; ++i) {
        int d = i * (i + 3) / 2;
        float rv = Lm[d];
        float sp = fmaxf(rv, 0.f) + log1pf(__expf(-fabsf(rv)));
        Lm[d] = sp;
        log_det += __logf(sp);
    }
    float corr[8] = {x1v[0], x1v[1], x1v[2], x1v[3], x2v[0], x2v[1], x2v[2], x2v[3]};
    float zv[8];
#pragma unroll
    for (int i = 0; i < 8; ++i) {
        float acc = corr[i];
#pragma unroll
        for (int j = 0; j < 8; ++j)
            if (j < i) acc -= Lm[i * (i + 1) / 2 + j] * zv[j];
        zv[i] = acc / Lm[i * (i + 1) / 2 + i];
    }
    float mahal = 0.f;
#pragma unroll
    for (int i = 0; i < 8; ++i) mahal += zv[i] * zv[i];
    const float LOG2PIf = 1.8378770664093453f;
    float lp  = -0.5f * (8.f * LOG2PIf + mahal) - log_det - fld;
    float ent = 0.5f * (8.f * (1.f + LOG2PIf)) + log_det + fld;

    if (quarter == 0) {
        *reinterpret_cast<float4*>(P.out + grow * 8)     = a0;
        *reinterpret_cast<float4*>(P.out + grow * 8 + 4) = a1;
        P.out[Bq * 8 + grow]  = lp;
        P.out[Bq * 9 + grow]  = ent;
        P.out[Bq * 10 + grow] = amv[r * 12 + 8];
    }
}

extern "C" void kernel_launch(void* const* d_in, const int* in_sizes, int n_in,
                              void* d_out, int out_size) {
    (void)n_in; (void)out_size;
    Params P;
    P.x      = (const float*)d_in[0];
    P.action = (const float*)d_in[1];
    P.z_rpo  = (const float*)d_in[2];
    P.cW1    = (const float*)d_in[3];
    P.cb1    = (const float*)d_in[4];
    P.c_rms  = (const float*)d_in[5];
    P.cW2    = (const float*)d_in[6];
    P.cb2    = (const float*)d_in[7];
    P.cW3    = (const float*)d_in[8];
    P.cb3    = (const float*)d_in[9];
    P.aW1    = (const float*)d_in[10];
    P.ab1    = (const float*)d_in[11];
    P.aW2    = (const float*)d_in[12];
    P.ab2    = (const float*)d_in[13];
    P.mW     = (const float*)d_in[14];
    P.mb     = (const float*)d_in[15];
    P.tW1    = (const float*)d_in[16];
    P.tb1    = (const float*)d_in[17];
    P.t_rms1 = (const float*)d_in[18];
    P.tW2    = (const float*)d_in[19];
    P.tb2    = (const float*)d_in[20];
    P.t_rms2 = (const float*)d_in[21];
    P.hW     = (const float*)d_in[22];
    P.hb     = (const float*)d_in[23];
    P.fW1    = (const float*)d_in[24];
    P.fb1    = (const float*)d_in[25];
    P.fW2    = (const float*)d_in[26];
    P.fb2    = (const float*)d_in[27];
    P.out    = (float*)d_out;
    P.B      = in_sizes[0] / OBS;

    prep_weights<<<(SCRATCH_F + 255) / 256, 256>>>(P);
    cudaFuncSetAttribute(fused_agent_tc,
                         cudaFuncAttributeMaxDynamicSharedMemorySize, SMEM_BYTES);
    fused_agent_tc<<<P.B / ROWS, THREADS, SMEM_BYTES>>>(P);
}